// round 1
// baseline (speedup 1.0000x reference)
#include <cuda_runtime.h>
#include <math.h>

namespace {
constexpr int kB = 8, kN = 4096, kL = 8, kE = 16384, kH = 256;
constexpr int kV = 32000, kOV = 512, kMaxSteps = 6;
constexpr int kM = kB * kN;        // 32768 rows (B*N)
constexpr int k4H = 4 * kH;        // 1024
}

// ---------------- scratch (static device allocations are allowed) -----------
__device__ float g_G0[(size_t)kV * k4H];     // embed_table @ Wi0  (131 MB)
__device__ float g_z [(size_t)kM * k4H];     // LSTM pre-activations (134 MB)
__device__ float g_h0[kM * kH];
__device__ float g_c0[kM * kH];
__device__ float g_h1[kM * kH];              // doubles as `se` after LSTM
__device__ float g_c1[kM * kH];
__device__ float g_new[kM * kH];             // GAT new embeddings
__device__ float g_keys[kM * kH];
__device__ float g_ak[kM];
__device__ float g_aq[kM];
__device__ float g_mx[kM];
__device__ float g_ss[kM];
__device__ float g_edge[kB * kE];
__device__ float g_ae[8];

// ---------------- fp32 GEMM: C[M,Nc] = sum_pairs A_p[M,256] @ W_p[256,Nc]
//                  (+ bias[Nc]) (+ gatherTab[gatherIdx[m*gidxStride]][:Nc]) ---
__global__ __launch_bounds__(256) void sgemm_kernel(
    int M, int Nc,
    const float* __restrict__ A0, const float* __restrict__ W0,
    const float* __restrict__ A1, const float* __restrict__ W1,
    int nPairs,
    const float* __restrict__ bias,
    const float* __restrict__ gatherTab, const int* __restrict__ gatherIdx,
    int gidxStride,
    float* __restrict__ C)
{
    constexpr int BM = 128, BN = 128, BK = 16, TM = 8, TN = 8;
    __shared__ float As[BK][BM + 4];
    __shared__ float Bs[BK][BN + 4];

    const int tid = threadIdx.x;
    const int tx = tid & 15;          // 0..15 -> N micro
    const int ty = tid >> 4;          // 0..15 -> M micro
    const int mBase = blockIdx.y * BM;
    const int nBase = blockIdx.x * BN;

    float acc[TM][TN];
#pragma unroll
    for (int i = 0; i < TM; i++)
#pragma unroll
        for (int j = 0; j < TN; j++) acc[i][j] = 0.f;

    const int aRow  = tid >> 2;       // 0..63
    const int aCol4 = tid & 3;        // 0..3  (float4 index in BK)
    const int bRow  = tid >> 5;       // 0..7
    const int bCol4 = tid & 31;       // 0..31 (float4 index in BN)

    for (int pair = 0; pair < nPairs; ++pair) {
        const float* A = pair ? A1 : A0;
        const float* W = pair ? W1 : W0;
        for (int kt = 0; kt < 256; kt += BK) {
#pragma unroll
            for (int i = 0; i < 2; i++) {
                int r = aRow + 64 * i;
                float4 v = *(const float4*)(A + (size_t)(mBase + r) * 256 + kt + aCol4 * 4);
                As[aCol4 * 4 + 0][r] = v.x;
                As[aCol4 * 4 + 1][r] = v.y;
                As[aCol4 * 4 + 2][r] = v.z;
                As[aCol4 * 4 + 3][r] = v.w;
            }
#pragma unroll
            for (int i = 0; i < 2; i++) {
                int r = bRow + 8 * i;
                float4 v = *(const float4*)(W + (size_t)(kt + r) * Nc + nBase + bCol4 * 4);
                Bs[r][bCol4 * 4 + 0] = v.x;
                Bs[r][bCol4 * 4 + 1] = v.y;
                Bs[r][bCol4 * 4 + 2] = v.z;
                Bs[r][bCol4 * 4 + 3] = v.w;
            }
            __syncthreads();
#pragma unroll
            for (int k = 0; k < BK; k++) {
                float ra[TM], rb[TN];
#pragma unroll
                for (int i = 0; i < TM; i++) ra[i] = As[k][ty * TM + i];
#pragma unroll
                for (int j = 0; j < TN; j++) rb[j] = Bs[k][tx * TN + j];
#pragma unroll
                for (int i = 0; i < TM; i++)
#pragma unroll
                    for (int j = 0; j < TN; j++) acc[i][j] += ra[i] * rb[j];
            }
            __syncthreads();
        }
    }

#pragma unroll
    for (int i = 0; i < TM; i++) {
        int m = mBase + ty * TM + i;
        const float* grow = nullptr;
        if (gatherTab) grow = gatherTab + (size_t)gatherIdx[(size_t)m * gidxStride] * Nc;
#pragma unroll
        for (int j = 0; j < TN; j += 4) {
            int n = nBase + tx * TN + j;
            float4 o;
            o.x = acc[i][j]; o.y = acc[i][j + 1]; o.z = acc[i][j + 2]; o.w = acc[i][j + 3];
            if (bias) {
                float4 bv = *(const float4*)(bias + n);
                o.x += bv.x; o.y += bv.y; o.z += bv.z; o.w += bv.w;
            }
            if (grow) {
                float4 gv = *(const float4*)(grow + n);
                o.x += gv.x; o.y += gv.y; o.z += gv.z; o.w += gv.w;
            }
            *(float4*)(C + (size_t)m * Nc + n) = o;
        }
    }
}

// ---------------- LSTM gate fusion: one block per row m --------------------
__device__ __forceinline__ float sigm(float x) { return 1.f / (1.f + expf(-x)); }

__global__ __launch_bounds__(256) void lstm_gates_kernel(
    const float* __restrict__ z, float* __restrict__ c, float* __restrict__ h)
{
    int m = blockIdx.x;
    int u = threadIdx.x;
    const float* zr = z + (size_t)m * k4H;
    float zi = zr[u], zf = zr[256 + u], zg = zr[512 + u], zo = zr[768 + u];
    size_t idx = (size_t)m * kH + u;
    float cn = sigm(zf) * c[idx] + sigm(zi) * tanhf(zg);
    c[idx] = cn;
    h[idx] = sigm(zo) * tanhf(cn);
}

// ---------------- GAT helpers ----------------------------------------------
__global__ void compute_ae_kernel(const float* __restrict__ edge_table,
                                  const float* __restrict__ Wa)
{
    int w = threadIdx.x >> 5, lane = threadIdx.x & 31;
    if (w >= 6) return;
    float s = 0.f;
    for (int hh = lane; hh < kH; hh += 32) s += edge_table[w * kH + hh] * Wa[hh];
#pragma unroll
    for (int o = 16; o; o >>= 1) s += __shfl_down_sync(0xffffffffu, s, o);
    if (!lane) g_ae[w] = s;
}

__global__ __launch_bounds__(256) void node_scores_kernel(const float* __restrict__ keys,
                                                          const float* __restrict__ Wa)
{
    __shared__ float sWa[2 * kH];
    int tid = threadIdx.x;
    for (int i = tid; i < 2 * kH; i += 256) sWa[i] = Wa[i];
    __syncthreads();
    int node = (blockIdx.x * 256 + tid) >> 5;
    int lane = tid & 31;
    const float* kr = keys + (size_t)node * kH;
    float s1 = 0.f, s2 = 0.f;
    for (int hh = lane; hh < kH; hh += 32) {
        float kv = kr[hh];
        s1 += kv * sWa[hh];
        s2 += kv * sWa[kH + hh];
    }
#pragma unroll
    for (int o = 16; o; o >>= 1) {
        s1 += __shfl_down_sync(0xffffffffu, s1, o);
        s2 += __shfl_down_sync(0xffffffffu, s2, o);
    }
    if (!lane) { g_ak[node] = s1; g_aq[node] = s2; }
}

__global__ void init_seg_kernel()
{
    int i = blockIdx.x * 256 + threadIdx.x;
    g_mx[i] = -INFINITY;
    g_ss[i] = 0.f;
}

__device__ __forceinline__ float atomicMaxF(float* addr, float val)
{
    if (val >= 0.f)
        return __int_as_float(atomicMax((int*)addr, __float_as_int(val)));
    else
        return __uint_as_float(atomicMin((unsigned int*)addr, __float_as_uint(val)));
}

__global__ __launch_bounds__(256) void edge_pass1(
    const int* __restrict__ src, const int* __restrict__ dst,
    const int* __restrict__ et, const int* __restrict__ steps,
    const float* __restrict__ ba, int step)
{
    int e = blockIdx.x * 256 + threadIdx.x;
    int b = e / kE;
    if (step >= steps[b]) return;
    int d = dst[e];
    float lg = g_ak[b * kN + src[e]] + g_ae[et[e]] + g_aq[b * kN + d] + ba[0];
    lg = fmaxf(0.2f * lg, lg);
    g_edge[e] = lg;
    atomicMaxF(&g_mx[b * kN + d], lg);
}

__global__ __launch_bounds__(256) void edge_pass2(
    const int* __restrict__ dst, const int* __restrict__ steps, int step)
{
    int e = blockIdx.x * 256 + threadIdx.x;
    int b = e / kE;
    if (step >= steps[b]) return;
    int d = dst[e];
    float ex = expf(g_edge[e] - g_mx[b * kN + d]);
    g_edge[e] = ex;
    atomicAdd(&g_ss[b * kN + d], ex);
}

__global__ __launch_bounds__(256) void edge_pass3(
    const int* __restrict__ src, const int* __restrict__ dst,
    const int* __restrict__ et, const int* __restrict__ steps,
    const float* __restrict__ edge_table, int step)
{
    int gid = blockIdx.x * 256 + threadIdx.x;
    int e = gid >> 5, lane = gid & 31;
    int b = e / kE;
    if (step >= steps[b]) return;
    int s = src[e], d = dst[e], t = et[e];
    float w = g_edge[e] / g_ss[b * kN + d];
    const float* kr = g_keys + (size_t)(b * kN + s) * kH;
    const float* er = edge_table + t * kH;
    float* orow = g_new + (size_t)(b * kN + d) * kH;
    for (int hh = lane; hh < kH; hh += 32)
        atomicAdd(&orow[hh], (kr[hh] + er[hh]) * w);
}

__global__ __launch_bounds__(256) void masked_copy_kernel(
    const int* __restrict__ steps, int step,
    const float4* __restrict__ srcv, float4* __restrict__ dstv)
{
    int i = blockIdx.x * 256 + threadIdx.x;
    int b = i / (kN * kH / 4);
    if (step < steps[b]) dstv[i] = srcv[i];
}

// ---------------- final gather + dense --------------------------------------
__global__ __launch_bounds__(256) void final_kernel(
    const float* __restrict__ se, const int* __restrict__ exit_index,
    const float* __restrict__ Wo, const float* __restrict__ bo,
    float* __restrict__ out)
{
    __shared__ float fin[kH];
    int b = blockIdx.x, tid = threadIdx.x;
    const float* row = se + ((size_t)b * kN + exit_index[b]) * kH;
    if (tid < kH) fin[tid] = row[tid];
    __syncthreads();
    for (int j = tid; j < kOV; j += 256) {
        float s = bo[j];
        for (int hh = 0; hh < kH; hh++) s += fin[hh] * Wo[(size_t)hh * kOV + j];
        out[b * kOV + j] = s;
    }
}

// ---------------- driver -----------------------------------------------------
extern "C" void kernel_launch(void* const* d_in, const int* in_sizes, int n_in,
                              void* d_out, int out_size)
{
    const int*   data       = (const int*)d_in[0];
    const int*   src        = (const int*)d_in[1];
    const int*   dst        = (const int*)d_in[2];
    const int*   et         = (const int*)d_in[3];
    const int*   steps      = (const int*)d_in[4];
    const int*   exit_index = (const int*)d_in[5];
    const float* embed      = (const float*)d_in[6];
    const float* Wi0        = (const float*)d_in[7];
    const float* Wh0        = (const float*)d_in[8];
    const float* b0         = (const float*)d_in[9];
    const float* Wi1        = (const float*)d_in[10];
    const float* Wh1        = (const float*)d_in[11];
    const float* b1         = (const float*)d_in[12];
    const float* Wk         = (const float*)d_in[13];
    const float* bk         = (const float*)d_in[14];
    const float* Wa         = (const float*)d_in[15];
    const float* ba         = (const float*)d_in[16];
    const float* edge_table = (const float*)d_in[17];
    const float* Wo         = (const float*)d_in[18];
    const float* bo         = (const float*)d_in[19];
    float* out = (float*)d_out;

    float *G0, *z, *h0, *c0, *h1, *c1, *nw, *keys;
    cudaGetSymbolAddress((void**)&G0,   g_G0);
    cudaGetSymbolAddress((void**)&z,    g_z);
    cudaGetSymbolAddress((void**)&h0,   g_h0);
    cudaGetSymbolAddress((void**)&c0,   g_c0);
    cudaGetSymbolAddress((void**)&h1,   g_h1);
    cudaGetSymbolAddress((void**)&c1,   g_c1);
    cudaGetSymbolAddress((void**)&nw,   g_new);
    cudaGetSymbolAddress((void**)&keys, g_keys);

    const size_t stateBytes = (size_t)kM * kH * sizeof(float);
    cudaMemsetAsync(h0, 0, stateBytes);
    cudaMemsetAsync(c0, 0, stateBytes);
    cudaMemsetAsync(h1, 0, stateBytes);
    cudaMemsetAsync(c1, 0, stateBytes);

    // Precompute G0 = embed_table @ Wi0  (so layer-0 input GEMMs become gathers)
    sgemm_kernel<<<dim3(k4H / 128, kV / 128), 256>>>(
        kV, k4H, embed, Wi0, nullptr, nullptr, 1,
        nullptr, nullptr, nullptr, 0, G0);

    // LSTM over L=8 timesteps, 2 layers
    for (int t = 0; t < kL; t++) {
        // layer 0: z = h0 @ Wh0 + G0[token] + b0
        sgemm_kernel<<<dim3(k4H / 128, kM / 128), 256>>>(
            kM, k4H, h0, Wh0, nullptr, nullptr, 1,
            b0, G0, data + t, kL, z);
        lstm_gates_kernel<<<kM, 256>>>(z, c0, h0);
        // layer 1: z = h0 @ Wi1 + h1 @ Wh1 + b1
        sgemm_kernel<<<dim3(k4H / 128, kM / 128), 256>>>(
            kM, k4H, h0, Wi1, h1, Wh1, 2,
            b1, nullptr, nullptr, 0, z);
        lstm_gates_kernel<<<kM, 256>>>(z, c1, h1);
    }
    float* se = h1;   // statement embeddings live in h1

    compute_ae_kernel<<<1, 256>>>(edge_table, Wa);

    for (int step = 0; step < kMaxSteps; step++) {
        // keys = se @ Wk + bk   (one big GEMM across all batches)
        sgemm_kernel<<<dim3(kH / 128, kM / 128), 256>>>(
            kM, kH, se, Wk, nullptr, nullptr, 1,
            bk, nullptr, nullptr, 0, keys);
        node_scores_kernel<<<kM / 8, 256>>>(keys, Wa);
        init_seg_kernel<<<kM / 256, 256>>>();
        cudaMemsetAsync(nw, 0, stateBytes);
        edge_pass1<<<kB * kE / 256, 256>>>(src, dst, et, steps, ba, step);
        edge_pass2<<<kB * kE / 256, 256>>>(dst, steps, step);
        edge_pass3<<<kB * kE * 32 / 256, 256>>>(src, dst, et, steps, edge_table, step);
        masked_copy_kernel<<<kM * kH / 4 / 256, 256>>>(
            steps, step, (const float4*)nw, (float4*)se);
    }

    final_kernel<<<kB, 256>>>(se, exit_index, Wo, bo, out);
}

// round 3
// speedup vs baseline: 1.9294x; 1.9294x over previous
#include <cuda_runtime.h>
#include <cuda_bf16.h>
#include <math.h>
#include <stdint.h>

namespace {
constexpr int kB = 8, kN = 4096, kL = 8, kE = 16384, kH = 256;
constexpr int kV = 32000, kOV = 512, kMaxSteps = 6;
constexpr int kM = kB * kN;        // 32768
constexpr int k4H = 4 * kH;        // 1024
constexpr int TILE_B = 10240;      // 128 rows * 80 bytes (32 bf16 + pad)
constexpr int GEMM_SMEM = 4 * TILE_B;   // A/B double buffered
}

// ---------------- scratch ---------------------------------------------------
__device__ float g_G0[(size_t)kV * k4H];
__device__ float g_z [(size_t)kM * k4H];
__device__ float g_c0[kM * kH];
__device__ float g_c1[kM * kH];
__device__ __nv_bfloat16 g_h0h[kM * kH], g_h0l[kM * kH];
__device__ __nv_bfloat16 g_h1h[kM * kH], g_h1l[kM * kH];   // doubles as se split
__device__ float g_se[kM * kH];
__device__ __nv_bfloat16 g_embh[(size_t)kV * kH], g_embl[(size_t)kV * kH];
__device__ __nv_bfloat16 g_Wi0Th[k4H * kH], g_Wi0Tl[k4H * kH];
__device__ __nv_bfloat16 g_Wh0Th[k4H * kH], g_Wh0Tl[k4H * kH];
__device__ __nv_bfloat16 g_Wi1Th[k4H * kH], g_Wi1Tl[k4H * kH];
__device__ __nv_bfloat16 g_Wh1Th[k4H * kH], g_Wh1Tl[k4H * kH];
__device__ __nv_bfloat16 g_WkTh[kH * kH],  g_WkTl[kH * kH];
__device__ float g_new[kM * kH];
__device__ float g_keys[kM * kH];
__device__ float g_ak[kM], g_aq[kM], g_mx[kM], g_ss[kM];
__device__ float g_edge[kB * kE];
__device__ float g_ae[8];

// ---------------- PTX helpers ----------------------------------------------
__device__ __forceinline__ uint32_t smem_u32(const void* p) {
    uint32_t a;
    asm("{ .reg .u64 t; cvta.to.shared.u64 t, %1; cvt.u32.u64 %0, t; }"
        : "=r"(a) : "l"(p));
    return a;
}
__device__ __forceinline__ void cpasync16(uint32_t dst, const void* src) {
    asm volatile("cp.async.cg.shared.global [%0], [%1], 16;"
                 :: "r"(dst), "l"(src) : "memory");
}
__device__ __forceinline__ void cp_commit() {
    asm volatile("cp.async.commit_group;" ::: "memory");
}
template <int N>
__device__ __forceinline__ void cp_wait() {
    asm volatile("cp.async.wait_group %0;" :: "n"(N) : "memory");
}
__device__ __forceinline__ void ldsm4(uint32_t* r, uint32_t a) {
    asm volatile("ldmatrix.sync.aligned.m8n8.x4.shared.b16 {%0,%1,%2,%3}, [%4];"
                 : "=r"(r[0]), "=r"(r[1]), "=r"(r[2]), "=r"(r[3]) : "r"(a));
}
__device__ __forceinline__ void mma16816(float* d, const uint32_t* a, const uint32_t* b) {
    asm volatile(
        "mma.sync.aligned.m16n8k16.row.col.f32.bf16.bf16.f32 "
        "{%0,%1,%2,%3}, {%4,%5,%6,%7}, {%8,%9}, {%0,%1,%2,%3};"
        : "+f"(d[0]), "+f"(d[1]), "+f"(d[2]), "+f"(d[3])
        : "r"(a[0]), "r"(a[1]), "r"(a[2]), "r"(a[3]), "r"(b[0]), "r"(b[1]));
}

// ---------------- split-bf16 HMMA GEMM ---------------------------------------
// C[M,NTotal](fp32) = sum_pairs A_p[M,256] @ B_p[N,256]^T  (+bias)(+gather row)
// 3-pass bf16 split: Ah*Bh + Al*Bh + Ah*Bl. Tile 128x128, K-chunk 32.
__global__ void __launch_bounds__(256, 2) mma_gemm(
    int M, int NTotal, int nPairs,
    const __nv_bfloat16* __restrict__ A0h, const __nv_bfloat16* __restrict__ A0l,
    const __nv_bfloat16* __restrict__ B0h, const __nv_bfloat16* __restrict__ B0l,
    const __nv_bfloat16* __restrict__ A1h, const __nv_bfloat16* __restrict__ A1l,
    const __nv_bfloat16* __restrict__ B1h, const __nv_bfloat16* __restrict__ B1l,
    const float* __restrict__ bias,
    const float* __restrict__ gatherTab, const int* __restrict__ gatherIdx, int gStride,
    float* __restrict__ C)
{
    extern __shared__ __align__(128) char smem[];
    const int tid = threadIdx.x, wid = tid >> 5, lane = tid & 31;
    const int mBase = blockIdx.y * 128, nBase = blockIdx.x * 128;
    const int wM = (wid & 3) * 32, wN = (wid >> 2) * 64;
    const uint32_t sbase = smem_u32(smem);

    float acc[2][8][4];
#pragma unroll
    for (int i = 0; i < 2; i++)
#pragma unroll
        for (int j = 0; j < 8; j++)
#pragma unroll
            for (int k = 0; k < 4; k++) acc[i][j][k] = 0.f;

    const int nChunks = nPairs * 24;    // 3 passes * 8 k-chunks per pair

    auto chunk_src = [&](int c, const __nv_bfloat16*& Ap, const __nv_bfloat16*& Bp,
                         int& kt) {
        int pair = c / 24, cc = c % 24, pass = cc >> 3;
        kt = (cc & 7) * 32;
        const __nv_bfloat16* Ah = pair ? A1h : A0h;
        const __nv_bfloat16* Al = pair ? A1l : A0l;
        const __nv_bfloat16* Bh = pair ? B1h : B0h;
        const __nv_bfloat16* Bl = pair ? B1l : B0l;
        Ap = (pass == 1) ? Al : Ah;
        Bp = (pass == 2) ? Bl : Bh;
    };

    auto load_chunk = [&](int c) {
        const __nv_bfloat16 *Ap, *Bp; int kt;
        chunk_src(c, Ap, Bp, kt);
        const uint32_t sA = sbase + (uint32_t)(c & 1) * (2 * TILE_B);
        const uint32_t sB = sA + TILE_B;
#pragma unroll
        for (int i = 0; i < 2; i++) {
            int idx = i * 256 + tid;
            int r = idx >> 2, cc4 = idx & 3;
            cpasync16(sA + r * 80 + cc4 * 16,
                      Ap + (size_t)(mBase + r) * 256 + kt + cc4 * 8);
            cpasync16(sB + r * 80 + cc4 * 16,
                      Bp + (size_t)(nBase + r) * 256 + kt + cc4 * 8);
        }
        cp_commit();
    };

    auto compute_chunk = [&](int c) {
        const uint32_t sA = sbase + (uint32_t)(c & 1) * (2 * TILE_B);
        const uint32_t sB = sA + TILE_B;
#pragma unroll
        for (int ks = 0; ks < 2; ks++) {
            uint32_t a[2][4];
#pragma unroll
            for (int mt = 0; mt < 2; mt++) {
                int row = wM + mt * 16 + (lane & 15);
                ldsm4(a[mt], sA + row * 80 + ((lane >> 4) * 16) + ks * 32);
            }
#pragma unroll
            for (int nt2 = 0; nt2 < 4; nt2++) {
                uint32_t b[4];
                int nrow = wN + nt2 * 16 + (lane & 7) + ((lane >> 4) << 3);
                ldsm4(b, sB + nrow * 80 + (((lane >> 3) & 1) * 16) + ks * 32);
                mma16816(acc[0][nt2 * 2 + 0], a[0], b + 0);
                mma16816(acc[0][nt2 * 2 + 1], a[0], b + 2);
                mma16816(acc[1][nt2 * 2 + 0], a[1], b + 0);
                mma16816(acc[1][nt2 * 2 + 1], a[1], b + 2);
            }
        }
    };

    load_chunk(0);
    for (int c = 0; c < nChunks - 1; ++c) {
        load_chunk(c + 1);
        cp_wait<1>();
        __syncthreads();
        compute_chunk(c);
        __syncthreads();
    }
    cp_wait<0>();
    __syncthreads();
    compute_chunk(nChunks - 1);

    // ---- epilogue: direct fp32 stores with bias + gather-add ----
#pragma unroll
    for (int mt = 0; mt < 2; mt++) {
        int r0 = mBase + wM + mt * 16 + (lane >> 2);
        int r1 = r0 + 8;
        const float* g0 = nullptr;
        const float* g1 = nullptr;
        if (gatherTab) {
            g0 = gatherTab + (size_t)gatherIdx[(size_t)r0 * gStride] * NTotal;
            g1 = gatherTab + (size_t)gatherIdx[(size_t)r1 * gStride] * NTotal;
        }
#pragma unroll
        for (int nt = 0; nt < 8; nt++) {
            int n = nBase + wN + nt * 8 + (lane & 3) * 2;
            float2 v0 = make_float2(acc[mt][nt][0], acc[mt][nt][1]);
            float2 v1 = make_float2(acc[mt][nt][2], acc[mt][nt][3]);
            if (bias) {
                float2 bv = *(const float2*)(bias + n);
                v0.x += bv.x; v0.y += bv.y; v1.x += bv.x; v1.y += bv.y;
            }
            if (g0) {
                float2 a0 = *(const float2*)(g0 + n);
                float2 a1 = *(const float2*)(g1 + n);
                v0.x += a0.x; v0.y += a0.y; v1.x += a1.x; v1.y += a1.y;
            }
            *(float2*)(C + (size_t)r0 * NTotal + n) = v0;
            *(float2*)(C + (size_t)r1 * NTotal + n) = v1;
        }
    }
}

// ---------------- weight transpose + bf16 split -----------------------------
__global__ void __launch_bounds__(256) transpose_split_kernel(
    const float* __restrict__ W, int K, int N,
    __nv_bfloat16* __restrict__ Th, __nv_bfloat16* __restrict__ Tl)
{
    __shared__ float t[32][33];
    int n0 = blockIdx.x * 32, k0 = blockIdx.y * 32;
    int tx = threadIdx.x & 31, ty = threadIdx.x >> 5;   // 32 x 8
#pragma unroll
    for (int i = 0; i < 32; i += 8)
        t[ty + i][tx] = W[(size_t)(k0 + ty + i) * N + n0 + tx];
    __syncthreads();
#pragma unroll
    for (int i = 0; i < 32; i += 8) {
        float v = t[tx][ty + i];             // W[k0+tx][n0+ty+i]
        int n = n0 + ty + i, k = k0 + tx;
        __nv_bfloat16 h = __float2bfloat16(v);
        Th[(size_t)n * K + k] = h;
        Tl[(size_t)n * K + k] = __float2bfloat16(v - __bfloat162float(h));
    }
}

// ---------------- fp32 -> bf16 hi/lo split ----------------------------------
__global__ void __launch_bounds__(256) split_kernel(
    const float4* __restrict__ x, __nv_bfloat162* __restrict__ h2,
    __nv_bfloat162* __restrict__ l2, int n4)
{
    int i = blockIdx.x * 256 + threadIdx.x;
    if (i >= n4) return;
    float4 v = x[i];
    __nv_bfloat16 hx = __float2bfloat16(v.x), hy = __float2bfloat16(v.y);
    __nv_bfloat16 hz = __float2bfloat16(v.z), hw = __float2bfloat16(v.w);
    __nv_bfloat162 a; a.x = hx; a.y = hy;
    __nv_bfloat162 b; b.x = hz; b.y = hw;
    h2[i * 2 + 0] = a; h2[i * 2 + 1] = b;
    __nv_bfloat162 c; c.x = __float2bfloat16(v.x - __bfloat162float(hx));
    c.y = __float2bfloat16(v.y - __bfloat162float(hy));
    __nv_bfloat162 d; d.x = __float2bfloat16(v.z - __bfloat162float(hz));
    d.y = __float2bfloat16(v.w - __bfloat162float(hw));
    l2[i * 2 + 0] = c; l2[i * 2 + 1] = d;
}

// ---------------- LSTM gates -------------------------------------------------
__device__ __forceinline__ float sigm(float x) { return 1.f / (1.f + expf(-x)); }

__global__ void __launch_bounds__(256) lstm_gates_kernel(
    const float* __restrict__ z, float* __restrict__ c,
    __nv_bfloat16* __restrict__ hh, __nv_bfloat16* __restrict__ hl,
    float* __restrict__ hf)
{
    int m = blockIdx.x, u = threadIdx.x;
    const float* zr = z + (size_t)m * k4H;
    float zi = zr[u], zf = zr[256 + u], zg = zr[512 + u], zo = zr[768 + u];
    size_t idx = (size_t)m * kH + u;
    float cn = sigm(zf) * c[idx] + sigm(zi) * tanhf(zg);
    c[idx] = cn;
    float hn = sigm(zo) * tanhf(cn);
    __nv_bfloat16 b = __float2bfloat16(hn);
    hh[idx] = b;
    hl[idx] = __float2bfloat16(hn - __bfloat162float(b));
    if (hf) hf[idx] = hn;
}

// ---------------- GAT helpers -------------------------------------------------
__global__ void compute_ae_kernel(const float* __restrict__ edge_table,
                                  const float* __restrict__ Wa)
{
    int w = threadIdx.x >> 5, lane = threadIdx.x & 31;
    if (w >= 6) return;
    float s = 0.f;
    for (int hh = lane; hh < kH; hh += 32) s += edge_table[w * kH + hh] * Wa[hh];
#pragma unroll
    for (int o = 16; o; o >>= 1) s += __shfl_down_sync(0xffffffffu, s, o);
    if (!lane) g_ae[w] = s;
}

__global__ void __launch_bounds__(256) node_scores_kernel(
    const float* __restrict__ keys, const float* __restrict__ Wa)
{
    __shared__ float sWa[2 * kH];
    int tid = threadIdx.x;
    for (int i = tid; i < 2 * kH; i += 256) sWa[i] = Wa[i];
    __syncthreads();
    int node = (blockIdx.x * 256 + tid) >> 5;
    int lane = tid & 31;
    const float* kr = keys + (size_t)node * kH;
    float s1 = 0.f, s2 = 0.f;
    for (int hh = lane; hh < kH; hh += 32) {
        float kv = kr[hh];
        s1 += kv * sWa[hh];
        s2 += kv * sWa[kH + hh];
    }
#pragma unroll
    for (int o = 16; o; o >>= 1) {
        s1 += __shfl_down_sync(0xffffffffu, s1, o);
        s2 += __shfl_down_sync(0xffffffffu, s2, o);
    }
    if (!lane) { g_ak[node] = s1; g_aq[node] = s2; }
}

__global__ void init_seg_kernel()
{
    int i = blockIdx.x * 256 + threadIdx.x;
    g_mx[i] = -INFINITY;
    g_ss[i] = 0.f;
}

__device__ __forceinline__ float atomicMaxF(float* addr, float val)
{
    if (val >= 0.f)
        return __int_as_float(atomicMax((int*)addr, __float_as_int(val)));
    else
        return __uint_as_float(atomicMin((unsigned int*)addr, __float_as_uint(val)));
}

__global__ void __launch_bounds__(256) edge_pass1(
    const int* __restrict__ src, const int* __restrict__ dst,
    const int* __restrict__ et, const int* __restrict__ steps,
    const float* __restrict__ ba, int step)
{
    int e = blockIdx.x * 256 + threadIdx.x;
    int b = e / kE;
    if (step >= steps[b]) return;
    int d = dst[e];
    float lg = g_ak[b * kN + src[e]] + g_ae[et[e]] + g_aq[b * kN + d] + ba[0];
    lg = fmaxf(0.2f * lg, lg);
    g_edge[e] = lg;
    atomicMaxF(&g_mx[b * kN + d], lg);
}

__global__ void __launch_bounds__(256) edge_pass2(
    const int* __restrict__ dst, const int* __restrict__ steps, int step)
{
    int e = blockIdx.x * 256 + threadIdx.x;
    int b = e / kE;
    if (step >= steps[b]) return;
    int d = dst[e];
    float ex = expf(g_edge[e] - g_mx[b * kN + d]);
    g_edge[e] = ex;
    atomicAdd(&g_ss[b * kN + d], ex);
}

__global__ void __launch_bounds__(256) edge_pass3(
    const int* __restrict__ src, const int* __restrict__ dst,
    const int* __restrict__ et, const int* __restrict__ steps,
    const float* __restrict__ edge_table, int step)
{
    int gid = blockIdx.x * 256 + threadIdx.x;
    int e = gid >> 5, lane = gid & 31;
    int b = e / kE;
    if (step >= steps[b]) return;
    int s = src[e], d = dst[e], t = et[e];
    float w = g_edge[e] / g_ss[b * kN + d];
    const float* kr = g_keys + (size_t)(b * kN + s) * kH;
    const float* er = edge_table + t * kH;
    float* orow = g_new + (size_t)(b * kN + d) * kH;
    for (int hh = lane; hh < kH; hh += 32)
        atomicAdd(&orow[hh], (kr[hh] + er[hh]) * w);
}

// masked copy: se(fp32) and se split(bf16 hi/lo) updated together
__global__ void __launch_bounds__(256) masked_copy_kernel(
    const int* __restrict__ steps, int step,
    const float4* __restrict__ nw, float4* __restrict__ se,
    __nv_bfloat162* __restrict__ seh, __nv_bfloat162* __restrict__ sel)
{
    int i = blockIdx.x * 256 + threadIdx.x;
    int b = i / (kN * kH / 4);
    if (step >= steps[b]) return;
    float4 v = nw[i];
    se[i] = v;
    __nv_bfloat16 hx = __float2bfloat16(v.x), hy = __float2bfloat16(v.y);
    __nv_bfloat16 hz = __float2bfloat16(v.z), hw = __float2bfloat16(v.w);
    __nv_bfloat162 a; a.x = hx; a.y = hy;
    __nv_bfloat162 bb; bb.x = hz; bb.y = hw;
    seh[i * 2 + 0] = a; seh[i * 2 + 1] = bb;
    __nv_bfloat162 c; c.x = __float2bfloat16(v.x - __bfloat162float(hx));
    c.y = __float2bfloat16(v.y - __bfloat162float(hy));
    __nv_bfloat162 d; d.x = __float2bfloat16(v.z - __bfloat162float(hz));
    d.y = __float2bfloat16(v.w - __bfloat162float(hw));
    sel[i * 2 + 0] = c; sel[i * 2 + 1] = d;
}

// ---------------- final gather + dense ---------------------------------------
__global__ void __launch_bounds__(256) final_kernel(
    const float* __restrict__ se, const int* __restrict__ exit_index,
    const float* __restrict__ Wo, const float* __restrict__ bo,
    float* __restrict__ out)
{
    __shared__ float fin[kH];
    int b = blockIdx.x, tid = threadIdx.x;
    const float* row = se + ((size_t)b * kN + exit_index[b]) * kH;
    if (tid < kH) fin[tid] = row[tid];
    __syncthreads();
    for (int j = tid; j < kOV; j += 256) {
        float s = bo[j];
        for (int hh = 0; hh < kH; hh++) s += fin[hh] * Wo[(size_t)hh * kOV + j];
        out[b * kOV + j] = s;
    }
}

// ---------------- driver ------------------------------------------------------
extern "C" void kernel_launch(void* const* d_in, const int* in_sizes, int n_in,
                              void* d_out, int out_size)
{
    const int*   data       = (const int*)d_in[0];
    const int*   src        = (const int*)d_in[1];
    const int*   dst        = (const int*)d_in[2];
    const int*   et         = (const int*)d_in[3];
    const int*   steps      = (const int*)d_in[4];
    const int*   exit_index = (const int*)d_in[5];
    const float* embed      = (const float*)d_in[6];
    const float* Wi0        = (const float*)d_in[7];
    const float* Wh0        = (const float*)d_in[8];
    const float* b0         = (const float*)d_in[9];
    const float* Wi1        = (const float*)d_in[10];
    const float* Wh1        = (const float*)d_in[11];
    const float* b1         = (const float*)d_in[12];
    const float* Wk         = (const float*)d_in[13];
    const float* bk         = (const float*)d_in[14];
    const float* Wa         = (const float*)d_in[15];
    const float* ba         = (const float*)d_in[16];
    const float* edge_table = (const float*)d_in[17];
    const float* Wo         = (const float*)d_in[18];
    const float* bo         = (const float*)d_in[19];
    float* out = (float*)d_out;

    float *G0, *z, *c0, *c1, *se, *nw, *keys;
    __nv_bfloat16 *h0h, *h0l, *h1h, *h1l, *embh, *embl;
    __nv_bfloat16 *Wi0Th, *Wi0Tl, *Wh0Th, *Wh0Tl, *Wi1Th, *Wi1Tl, *Wh1Th, *Wh1Tl, *WkTh, *WkTl;
    cudaGetSymbolAddress((void**)&G0,   g_G0);
    cudaGetSymbolAddress((void**)&z,    g_z);
    cudaGetSymbolAddress((void**)&c0,   g_c0);
    cudaGetSymbolAddress((void**)&c1,   g_c1);
    cudaGetSymbolAddress((void**)&se,   g_se);
    cudaGetSymbolAddress((void**)&nw,   g_new);
    cudaGetSymbolAddress((void**)&keys, g_keys);
    cudaGetSymbolAddress((void**)&h0h,  g_h0h);
    cudaGetSymbolAddress((void**)&h0l,  g_h0l);
    cudaGetSymbolAddress((void**)&h1h,  g_h1h);
    cudaGetSymbolAddress((void**)&h1l,  g_h1l);
    cudaGetSymbolAddress((void**)&embh, g_embh);
    cudaGetSymbolAddress((void**)&embl, g_embl);
    cudaGetSymbolAddress((void**)&Wi0Th, g_Wi0Th);
    cudaGetSymbolAddress((void**)&Wi0Tl, g_Wi0Tl);
    cudaGetSymbolAddress((void**)&Wh0Th, g_Wh0Th);
    cudaGetSymbolAddress((void**)&Wh0Tl, g_Wh0Tl);
    cudaGetSymbolAddress((void**)&Wi1Th, g_Wi1Th);
    cudaGetSymbolAddress((void**)&Wi1Tl, g_Wi1Tl);
    cudaGetSymbolAddress((void**)&Wh1Th, g_Wh1Th);
    cudaGetSymbolAddress((void**)&Wh1Tl, g_Wh1Tl);
    cudaGetSymbolAddress((void**)&WkTh, g_WkTh);
    cudaGetSymbolAddress((void**)&WkTl, g_WkTl);

    cudaFuncSetAttribute(mma_gemm, cudaFuncAttributeMaxDynamicSharedMemorySize, GEMM_SMEM);

    const size_t stateBytes = (size_t)kM * kH * sizeof(float);
    cudaMemsetAsync(c0, 0, stateBytes);
    cudaMemsetAsync(c1, 0, stateBytes);
    cudaMemsetAsync(h0h, 0, (size_t)kM * kH * 2);
    cudaMemsetAsync(h0l, 0, (size_t)kM * kH * 2);
    cudaMemsetAsync(h1h, 0, (size_t)kM * kH * 2);
    cudaMemsetAsync(h1l, 0, (size_t)kM * kH * 2);

    // weight prep: transpose + split
    transpose_split_kernel<<<dim3(k4H / 32, kH / 32), 256>>>(Wi0, kH, k4H, Wi0Th, Wi0Tl);
    transpose_split_kernel<<<dim3(k4H / 32, kH / 32), 256>>>(Wh0, kH, k4H, Wh0Th, Wh0Tl);
    transpose_split_kernel<<<dim3(k4H / 32, kH / 32), 256>>>(Wi1, kH, k4H, Wi1Th, Wi1Tl);
    transpose_split_kernel<<<dim3(k4H / 32, kH / 32), 256>>>(Wh1, kH, k4H, Wh1Th, Wh1Tl);
    transpose_split_kernel<<<dim3(kH / 32,  kH / 32), 256>>>(Wk,  kH, kH,  WkTh,  WkTl);
    split_kernel<<<(kV * kH / 4 + 255) / 256, 256>>>(
        (const float4*)embed, (__nv_bfloat162*)embh, (__nv_bfloat162*)embl, kV * kH / 4);

    // G0 = embed @ Wi0   [32000, 1024]
    mma_gemm<<<dim3(k4H / 128, kV / 128), 256, GEMM_SMEM>>>(
        kV, k4H, 1, embh, embl, Wi0Th, Wi0Tl,
        nullptr, nullptr, nullptr, nullptr,
        nullptr, nullptr, nullptr, 0, G0);

    // LSTM over L=8 timesteps, 2 layers
    for (int t = 0; t < kL; t++) {
        mma_gemm<<<dim3(k4H / 128, kM / 128), 256, GEMM_SMEM>>>(
            kM, k4H, 1, h0h, h0l, Wh0Th, Wh0Tl,
            nullptr, nullptr, nullptr, nullptr,
            b0, G0, data + t, kL, z);
        lstm_gates_kernel<<<kM, 256>>>(z, c0, h0h, h0l, nullptr);
        mma_gemm<<<dim3(k4H / 128, kM / 128), 256, GEMM_SMEM>>>(
            kM, k4H, 2, h0h, h0l, Wi1Th, Wi1Tl,
            h1h, h1l, Wh1Th, Wh1Tl,
            b1, nullptr, nullptr, 0, z);
        lstm_gates_kernel<<<kM, 256>>>(z, c1, h1h, h1l, (t == kL - 1) ? se : nullptr);
    }

    compute_ae_kernel<<<1, 256>>>(edge_table, Wa);

    for (int step = 0; step < kMaxSteps; step++) {
        // keys = se @ Wk + bk  (se split lives in h1h/h1l)
        mma_gemm<<<dim3(kH / 128, kM / 128), 256, GEMM_SMEM>>>(
            kM, kH, 1, h1h, h1l, WkTh, WkTl,
            nullptr, nullptr, nullptr, nullptr,
            bk, nullptr, nullptr, 0, keys);
        node_scores_kernel<<<kM / 8, 256>>>(keys, Wa);
        init_seg_kernel<<<kM / 256, 256>>>();
        cudaMemsetAsync(nw, 0, stateBytes);
        edge_pass1<<<kB * kE / 256, 256>>>(src, dst, et, steps, ba, step);
        edge_pass2<<<kB * kE / 256, 256>>>(dst, steps, step);
        edge_pass3<<<kB * kE * 32 / 256, 256>>>(src, dst, et, steps, edge_table, step);
        masked_copy_kernel<<<kM * kH / 4 / 256, 256>>>(
            steps, step, (const float4*)nw, (float4*)se,
            (__nv_bfloat162*)h1h, (__nv_bfloat162*)h1l);
    }

    final_kernel<<<kB, 256>>>(se, exit_index, Wo, bo, out);
}

// round 4
// speedup vs baseline: 2.1182x; 1.0978x over previous
#include <cuda_runtime.h>
#include <cuda_fp16.h>
#include <math.h>
#include <stdint.h>

namespace {
constexpr int kB = 8, kN = 4096, kL = 8, kE = 16384, kH = 256;
constexpr int kV = 32000, kOV = 512, kMaxSteps = 6;
constexpr int kM = kB * kN;        // 32768
constexpr int k4H = 4 * kH;        // 1024
constexpr int TILE_B = 10240;      // 128 rows * 80 bytes (32 fp16 + pad)
constexpr int GEMM_SMEM = 4 * TILE_B;   // A/B double buffered
}

// ---------------- scratch ---------------------------------------------------
__device__ float g_G0[(size_t)kV * k4H];          // embed @ Wi0 (gate-permuted cols)
__device__ float g_c0[kM * kH], g_c1[kM * kH];
__device__ __half g_h0h[2][kM * kH], g_h0l[2][kM * kH];
__device__ __half g_h1h[2][kM * kH], g_h1l[2][kM * kH];
__device__ float g_se[kM * kH];
__device__ __half g_embh[(size_t)kV * kH], g_embl[(size_t)kV * kH];
__device__ __half g_Wi0T[k4H * kH], g_Wh0T[k4H * kH];
__device__ __half g_Wi1T[k4H * kH], g_Wh1T[k4H * kH];
__device__ __half g_WkT[kH * kH];
__device__ float g_bP0[k4H], g_bP1[k4H];
__device__ float g_new[kM * kH];
__device__ float g_keys[kM * kH];
__device__ float g_ak[kM], g_aq[kM], g_mx[kM], g_ss[kM];
__device__ float g_edge[kB * kE];
__device__ float g_ae[8];

// ---------------- PTX helpers ----------------------------------------------
__device__ __forceinline__ uint32_t smem_u32(const void* p) {
    uint32_t a;
    asm("{ .reg .u64 t; cvta.to.shared.u64 t, %1; cvt.u32.u64 %0, t; }"
        : "=r"(a) : "l"(p));
    return a;
}
__device__ __forceinline__ void cpasync16(uint32_t dst, const void* src) {
    asm volatile("cp.async.cg.shared.global [%0], [%1], 16;"
                 :: "r"(dst), "l"(src) : "memory");
}
__device__ __forceinline__ void cp_commit() {
    asm volatile("cp.async.commit_group;" ::: "memory");
}
template <int N>
__device__ __forceinline__ void cp_wait() {
    asm volatile("cp.async.wait_group %0;" :: "n"(N) : "memory");
}
__device__ __forceinline__ void ldsm4(uint32_t* r, uint32_t a) {
    asm volatile("ldmatrix.sync.aligned.m8n8.x4.shared.b16 {%0,%1,%2,%3}, [%4];"
                 : "=r"(r[0]), "=r"(r[1]), "=r"(r[2]), "=r"(r[3]) : "r"(a));
}
__device__ __forceinline__ void mma16816(float* d, const uint32_t* a, const uint32_t* b) {
    asm volatile(
        "mma.sync.aligned.m16n8k16.row.col.f32.f16.f16.f32 "
        "{%0,%1,%2,%3}, {%4,%5,%6,%7}, {%8,%9}, {%0,%1,%2,%3};"
        : "+f"(d[0]), "+f"(d[1]), "+f"(d[2]), "+f"(d[3])
        : "r"(a[0]), "r"(a[1]), "r"(a[2]), "r"(a[3]), "r"(b[0]), "r"(b[1]));
}
__device__ __forceinline__ float sigm(float x) { return 1.f / (1.f + expf(-x)); }

// ---------------- shared GEMM mainloop pieces --------------------------------
// SMEM tile: 128 rows * 80B (32 fp16 + 16B pad). A/B double-buffered.
#define GEMM_PROLOGUE                                                            \
    extern __shared__ __align__(128) char smem[];                               \
    const int tid = threadIdx.x, wid = tid >> 5, lane = tid & 31;               \
    const int mBase = blockIdx.y * 128, nBase = blockIdx.x * 128;               \
    const int wM = (wid & 3) * 32, wN = (wid >> 2) * 64;                        \
    const uint32_t sbase = smem_u32(smem);                                      \
    float acc[2][8][4];                                                         \
    _Pragma("unroll") for (int i = 0; i < 2; i++)                               \
    _Pragma("unroll") for (int j = 0; j < 8; j++)                               \
    _Pragma("unroll") for (int k = 0; k < 4; k++) acc[i][j][k] = 0.f;

__device__ __forceinline__ void load_tiles(uint32_t sbase, int buf, int tid,
        const __half* __restrict__ Ap, const __half* __restrict__ Bp,
        int mBase, int nBase, int kt) {
    const uint32_t sA = sbase + (uint32_t)buf * (2 * TILE_B);
    const uint32_t sB = sA + TILE_B;
#pragma unroll
    for (int i = 0; i < 2; i++) {
        int idx = i * 256 + tid;
        int r = idx >> 2, cc4 = idx & 3;
        cpasync16(sA + r * 80 + cc4 * 16,
                  Ap + (size_t)(mBase + r) * 256 + kt + cc4 * 8);
        cpasync16(sB + r * 80 + cc4 * 16,
                  Bp + (size_t)(nBase + r) * 256 + kt + cc4 * 8);
    }
    cp_commit();
}

__device__ __forceinline__ void compute_tiles(uint32_t sbase, int buf,
        int wM, int wN, int lane, float acc[2][8][4]) {
    const uint32_t sA = sbase + (uint32_t)buf * (2 * TILE_B);
    const uint32_t sB = sA + TILE_B;
#pragma unroll
    for (int ks = 0; ks < 2; ks++) {
        uint32_t a[2][4];
#pragma unroll
        for (int mt = 0; mt < 2; mt++) {
            int row = wM + mt * 16 + (lane & 15);
            ldsm4(a[mt], sA + row * 80 + ((lane >> 4) * 16) + ks * 32);
        }
#pragma unroll
        for (int nt2 = 0; nt2 < 4; nt2++) {
            uint32_t b[4];
            int nrow = wN + nt2 * 16 + (lane & 7) + ((lane >> 4) << 3);
            ldsm4(b, sB + nrow * 80 + (((lane >> 3) & 1) * 16) + ks * 32);
            mma16816(acc[0][nt2 * 2 + 0], a[0], b + 0);
            mma16816(acc[0][nt2 * 2 + 1], a[0], b + 2);
            mma16816(acc[1][nt2 * 2 + 0], a[1], b + 0);
            mma16816(acc[1][nt2 * 2 + 1], a[1], b + 2);
        }
    }
}

// ---------------- generic 2-pass fp16 GEMM (G0 precompute, keys) -------------
// C[M,NTotal] = (Ah+Al)[M,256] @ B[N,256]^T  + bias
__global__ void __launch_bounds__(256, 2) mma_gemm(
    int M, int NTotal,
    const __half* __restrict__ Ah, const __half* __restrict__ Al,
    const __half* __restrict__ B,
    const float* __restrict__ bias, float* __restrict__ C)
{
    GEMM_PROLOGUE
    const int nChunks = 16;   // 2 passes * 8 k-chunks
    auto srcA = [&](int c) { return (c >> 3) ? Al : Ah; };
    load_tiles(sbase, 0, tid, srcA(0), B, mBase, nBase, 0);
    for (int c = 0; c < nChunks - 1; ++c) {
        load_tiles(sbase, (c + 1) & 1, tid, srcA(c + 1), B, mBase, nBase,
                   ((c + 1) & 7) * 32);
        cp_wait<1>();
        __syncthreads();
        compute_tiles(sbase, c & 1, wM, wN, lane, acc);
        __syncthreads();
    }
    cp_wait<0>();
    __syncthreads();
    compute_tiles(sbase, (nChunks - 1) & 1, wM, wN, lane, acc);

#pragma unroll
    for (int mt = 0; mt < 2; mt++) {
        int r0 = mBase + wM + mt * 16 + (lane >> 2);
        int r1 = r0 + 8;
#pragma unroll
        for (int nt = 0; nt < 8; nt++) {
            int n = nBase + wN + nt * 8 + (lane & 3) * 2;
            float2 v0 = make_float2(acc[mt][nt][0], acc[mt][nt][1]);
            float2 v1 = make_float2(acc[mt][nt][2], acc[mt][nt][3]);
            if (bias) {
                float2 bv = *(const float2*)(bias + n);
                v0.x += bv.x; v0.y += bv.y; v1.x += bv.x; v1.y += bv.y;
            }
            *(float2*)(C + (size_t)r0 * NTotal + n) = v0;
            *(float2*)(C + (size_t)r1 * NTotal + n) = v1;
        }
    }
}

// ---------------- fused LSTM GEMM + gates -------------------------------------
// z = sum_pairs (Aph+Apl) @ Bp^T + biasP (+ G0[token] gather), gate-interleaved
// layout (col n -> gate n&3 of unit n>>2). Then applies LSTM cell in-epilogue:
// c = sig(zf)*c + sig(zi)*tanh(zg);  h = sig(zo)*tanh(c) -> fp16 hi/lo (+se).
__global__ void __launch_bounds__(256, 2) mma_lstm(
    int nPairs,
    const __half* __restrict__ A0h, const __half* __restrict__ A0l,
    const __half* __restrict__ B0,
    const __half* __restrict__ A1h, const __half* __restrict__ A1l,
    const __half* __restrict__ B1,
    const float* __restrict__ biasP,
    const float* __restrict__ G0, const int* __restrict__ tokIdx, int tokStride,
    float* __restrict__ c,
    __half* __restrict__ outh, __half* __restrict__ outl,
    float* __restrict__ seOut)
{
    GEMM_PROLOGUE
    const int nChunks = nPairs * 16;
    auto srcs = [&](int cc, const __half*& Ap, const __half*& Bp, int& kt) {
        int pair = cc >> 4, q = cc & 15;
        kt = (q & 7) * 32;
        Ap = pair ? ((q >> 3) ? A1l : A1h) : ((q >> 3) ? A0l : A0h);
        Bp = pair ? B1 : B0;
    };
    {
        const __half *Ap, *Bp; int kt;
        srcs(0, Ap, Bp, kt);
        load_tiles(sbase, 0, tid, Ap, Bp, mBase, nBase, kt);
    }
    for (int cc = 0; cc < nChunks - 1; ++cc) {
        const __half *Ap, *Bp; int kt;
        srcs(cc + 1, Ap, Bp, kt);
        load_tiles(sbase, (cc + 1) & 1, tid, Ap, Bp, mBase, nBase, kt);
        cp_wait<1>();
        __syncthreads();
        compute_tiles(sbase, cc & 1, wM, wN, lane, acc);
        __syncthreads();
    }
    cp_wait<0>();
    __syncthreads();
    compute_tiles(sbase, (nChunks - 1) & 1, wM, wN, lane, acc);

    // ---- fused epilogue: bias + gather + LSTM cell ----
#pragma unroll
    for (int mt = 0; mt < 2; mt++) {
        int r0 = mBase + wM + mt * 16 + (lane >> 2);
        int r1 = r0 + 8;
        const float *g0 = nullptr, *g1 = nullptr;
        if (G0) {
            g0 = G0 + (size_t)tokIdx[(size_t)r0 * tokStride] * k4H;
            g1 = G0 + (size_t)tokIdx[(size_t)r1 * tokStride] * k4H;
        }
#pragma unroll
        for (int nt = 0; nt < 8; nt++) {
            int n = nBase + wN + nt * 8 + (lane & 3) * 2;
            float z0 = acc[mt][nt][0] + biasP[n];
            float z1 = acc[mt][nt][1] + biasP[n + 1];
            float z2 = acc[mt][nt][2] + biasP[n];
            float z3 = acc[mt][nt][3] + biasP[n + 1];
            if (g0) {
                z0 += g0[n]; z1 += g0[n + 1];
                z2 += g1[n]; z3 += g1[n + 1];
            }
            // lane pair (lane^1) exchange: even lanes hold (i,f), odd (g,o)
            float e0 = __shfl_xor_sync(0xffffffffu, z0, 1);
            float e1 = __shfl_xor_sync(0xffffffffu, z1, 1);
            float e2 = __shfl_xor_sync(0xffffffffu, z2, 1);
            float e3 = __shfl_xor_sync(0xffffffffu, z3, 1);
            bool evn = (lane & 1) == 0;
            int row = evn ? r0 : r1;
            float zi = evn ? z0 : e2;
            float zf = evn ? z1 : e3;
            float zg = evn ? e0 : z2;
            float zo = evn ? e1 : z3;
            int uG = ((nBase + wN + nt * 8) >> 2) + ((lane & 3) >> 1);
            size_t idx = (size_t)row * kH + uG;
            float cn = sigm(zf) * c[idx] + sigm(zi) * tanhf(zg);
            c[idx] = cn;
            float hn = sigm(zo) * tanhf(cn);
            __half hb = __float2half(hn);
            outh[idx] = hb;
            outl[idx] = __float2half(hn - __half2float(hb));
            if (seOut) seOut[idx] = hn;
        }
    }
}

// ---------------- weight prep -------------------------------------------------
// perm=1: T[n][k] = W[k][(n&3)*kH + (n>>2)]  (gate-interleaved transpose)
// perm=0: T[n][k] = W[k][n]
__global__ void __launch_bounds__(256) transpose_f16_kernel(
    const float* __restrict__ W, int N, int perm, __half* __restrict__ T)
{
    int n = blockIdx.x * 8 + (threadIdx.x >> 5);
    int lane = threadIdx.x & 31;
    int col = perm ? (n & 3) * kH + (n >> 2) : n;
#pragma unroll
    for (int kk = lane; kk < kH; kk += 32)
        T[(size_t)n * kH + kk] = __float2half(W[(size_t)kk * N + col]);
}

__global__ void perm_bias_kernel(const float* __restrict__ b, float* __restrict__ bP)
{
    int n = blockIdx.x * 256 + threadIdx.x;
    if (n < k4H) bP[n] = b[(n & 3) * kH + (n >> 2)];
}

// fp32 -> fp16 hi/lo split (embed table)
__global__ void __launch_bounds__(256) split_kernel(
    const float4* __restrict__ x, __half2* __restrict__ h2,
    __half2* __restrict__ l2, int n4)
{
    int i = blockIdx.x * 256 + threadIdx.x;
    if (i >= n4) return;
    float4 v = x[i];
    __half hx = __float2half(v.x), hy = __float2half(v.y);
    __half hz = __float2half(v.z), hw = __float2half(v.w);
    h2[i * 2 + 0] = __halves2half2(hx, hy);
    h2[i * 2 + 1] = __halves2half2(hz, hw);
    l2[i * 2 + 0] = __halves2half2(__float2half(v.x - __half2float(hx)),
                                   __float2half(v.y - __half2float(hy)));
    l2[i * 2 + 1] = __halves2half2(__float2half(v.z - __half2float(hz)),
                                   __float2half(v.w - __half2float(hw)));
}

// ---------------- GAT helpers -------------------------------------------------
__global__ void compute_ae_kernel(const float* __restrict__ edge_table,
                                  const float* __restrict__ Wa)
{
    int w = threadIdx.x >> 5, lane = threadIdx.x & 31;
    if (w >= 6) return;
    float s = 0.f;
    for (int hh = lane; hh < kH; hh += 32) s += edge_table[w * kH + hh] * Wa[hh];
#pragma unroll
    for (int o = 16; o; o >>= 1) s += __shfl_down_sync(0xffffffffu, s, o);
    if (!lane) g_ae[w] = s;
}

__global__ void __launch_bounds__(256) node_scores_kernel(
    const float* __restrict__ keys, const float* __restrict__ Wa)
{
    __shared__ float sWa[2 * kH];
    int tid = threadIdx.x;
    for (int i = tid; i < 2 * kH; i += 256) sWa[i] = Wa[i];
    __syncthreads();
    int node = (blockIdx.x * 256 + tid) >> 5;
    int lane = tid & 31;
    const float* kr = keys + (size_t)node * kH;
    float s1 = 0.f, s2 = 0.f;
    for (int hh = lane; hh < kH; hh += 32) {
        float kv = kr[hh];
        s1 += kv * sWa[hh];
        s2 += kv * sWa[kH + hh];
    }
#pragma unroll
    for (int o = 16; o; o >>= 1) {
        s1 += __shfl_down_sync(0xffffffffu, s1, o);
        s2 += __shfl_down_sync(0xffffffffu, s2, o);
    }
    if (!lane) { g_ak[node] = s1; g_aq[node] = s2; }
}

__global__ void init_seg_kernel()
{
    int i = blockIdx.x * 256 + threadIdx.x;
    g_mx[i] = -INFINITY;
    g_ss[i] = 0.f;
}

__device__ __forceinline__ float atomicMaxF(float* addr, float val)
{
    if (val >= 0.f)
        return __int_as_float(atomicMax((int*)addr, __float_as_int(val)));
    else
        return __uint_as_float(atomicMin((unsigned int*)addr, __float_as_uint(val)));
}

__global__ void __launch_bounds__(256) edge_pass1(
    const int* __restrict__ src, const int* __restrict__ dst,
    const int* __restrict__ et, const int* __restrict__ steps,
    const float* __restrict__ ba, int step)
{
    int e = blockIdx.x * 256 + threadIdx.x;
    int b = e / kE;
    if (step >= steps[b]) return;
    int d = dst[e];
    float lg = g_ak[b * kN + src[e]] + g_ae[et[e]] + g_aq[b * kN + d] + ba[0];
    lg = fmaxf(0.2f * lg, lg);
    g_edge[e] = lg;
    atomicMaxF(&g_mx[b * kN + d], lg);
}

__global__ void __launch_bounds__(256) edge_pass2(
    const int* __restrict__ dst, const int* __restrict__ steps, int step)
{
    int e = blockIdx.x * 256 + threadIdx.x;
    int b = e / kE;
    if (step >= steps[b]) return;
    int d = dst[e];
    float ex = expf(g_edge[e] - g_mx[b * kN + d]);
    g_edge[e] = ex;
    atomicAdd(&g_ss[b * kN + d], ex);
}

__global__ void __launch_bounds__(256) edge_pass3(
    const int* __restrict__ src, const int* __restrict__ dst,
    const int* __restrict__ et, const int* __restrict__ steps,
    const float* __restrict__ edge_table, int step)
{
    int gid = blockIdx.x * 256 + threadIdx.x;
    int e = gid >> 5, lane = gid & 31;
    int b = e / kE;
    if (step >= steps[b]) return;
    int s = src[e], d = dst[e], t = et[e];
    float w = g_edge[e] / g_ss[b * kN + d];
    const float* kr = g_keys + (size_t)(b * kN + s) * kH;
    const float* er = edge_table + t * kH;
    float* orow = g_new + (size_t)(b * kN + d) * kH;
    for (int hh = lane; hh < kH; hh += 32)
        atomicAdd(&orow[hh], (kr[hh] + er[hh]) * w);
}

// masked copy: se(fp32) and se split(fp16 hi/lo) updated together
__global__ void __launch_bounds__(256) masked_copy_kernel(
    const int* __restrict__ steps, int step,
    const float4* __restrict__ nw, float4* __restrict__ se,
    __half2* __restrict__ seh, __half2* __restrict__ sel)
{
    int i = blockIdx.x * 256 + threadIdx.x;
    int b = i / (kN * kH / 4);
    if (step >= steps[b]) return;
    float4 v = nw[i];
    se[i] = v;
    __half hx = __float2half(v.x), hy = __float2half(v.y);
    __half hz = __float2half(v.z), hw = __float2half(v.w);
    seh[i * 2 + 0] = __halves2half2(hx, hy);
    seh[i * 2 + 1] = __halves2half2(hz, hw);
    sel[i * 2 + 0] = __halves2half2(__float2half(v.x - __half2float(hx)),
                                    __float2half(v.y - __half2float(hy)));
    sel[i * 2 + 1] = __halves2half2(__float2half(v.z - __half2float(hz)),
                                    __float2half(v.w - __half2float(hw)));
}

// ---------------- final gather + dense ---------------------------------------
__global__ void __launch_bounds__(256) final_kernel(
    const float* __restrict__ se, const int* __restrict__ exit_index,
    const float* __restrict__ Wo, const float* __restrict__ bo,
    float* __restrict__ out)
{
    __shared__ float fin[kH];
    int b = blockIdx.x, tid = threadIdx.x;
    const float* row = se + ((size_t)b * kN + exit_index[b]) * kH;
    if (tid < kH) fin[tid] = row[tid];
    __syncthreads();
    for (int j = tid; j < kOV; j += 256) {
        float s = bo[j];
        for (int hh = 0; hh < kH; hh++) s += fin[hh] * Wo[(size_t)hh * kOV + j];
        out[b * kOV + j] = s;
    }
}

// ---------------- driver ------------------------------------------------------
extern "C" void kernel_launch(void* const* d_in, const int* in_sizes, int n_in,
                              void* d_out, int out_size)
{
    const int*   data       = (const int*)d_in[0];
    const int*   src        = (const int*)d_in[1];
    const int*   dst        = (const int*)d_in[2];
    const int*   et         = (const int*)d_in[3];
    const int*   steps      = (const int*)d_in[4];
    const int*   exit_index = (const int*)d_in[5];
    const float* embed      = (const float*)d_in[6];
    const float* Wi0        = (const float*)d_in[7];
    const float* Wh0        = (const float*)d_in[8];
    const float* b0         = (const float*)d_in[9];
    const float* Wi1        = (const float*)d_in[10];
    const float* Wh1        = (const float*)d_in[11];
    const float* b1         = (const float*)d_in[12];
    const float* Wk         = (const float*)d_in[13];
    const float* bk         = (const float*)d_in[14];
    const float* Wa         = (const float*)d_in[15];
    const float* ba         = (const float*)d_in[16];
    const float* edge_table = (const float*)d_in[17];
    const float* Wo         = (const float*)d_in[18];
    const float* bo         = (const float*)d_in[19];
    float* out = (float*)d_out;

    float *G0, *c0, *c1, *se, *nw, *keys, *bP0, *bP1;
    __half *h0h, *h0l, *h1h, *h1l, *embh, *embl;
    __half *Wi0T, *Wh0T, *Wi1T, *Wh1T, *WkT;
    cudaGetSymbolAddress((void**)&G0,   g_G0);
    cudaGetSymbolAddress((void**)&c0,   g_c0);
    cudaGetSymbolAddress((void**)&c1,   g_c1);
    cudaGetSymbolAddress((void**)&se,   g_se);
    cudaGetSymbolAddress((void**)&nw,   g_new);
    cudaGetSymbolAddress((void**)&keys, g_keys);
    cudaGetSymbolAddress((void**)&h0h,  g_h0h);
    cudaGetSymbolAddress((void**)&h0l,  g_h0l);
    cudaGetSymbolAddress((void**)&h1h,  g_h1h);
    cudaGetSymbolAddress((void**)&h1l,  g_h1l);
    cudaGetSymbolAddress((void**)&embh, g_embh);
    cudaGetSymbolAddress((void**)&embl, g_embl);
    cudaGetSymbolAddress((void**)&Wi0T, g_Wi0T);
    cudaGetSymbolAddress((void**)&Wh0T, g_Wh0T);
    cudaGetSymbolAddress((void**)&Wi1T, g_Wi1T);
    cudaGetSymbolAddress((void**)&Wh1T, g_Wh1T);
    cudaGetSymbolAddress((void**)&WkT,  g_WkT);
    cudaGetSymbolAddress((void**)&bP0,  g_bP0);
    cudaGetSymbolAddress((void**)&bP1,  g_bP1);

    cudaFuncSetAttribute(mma_gemm, cudaFuncAttributeMaxDynamicSharedMemorySize, GEMM_SMEM);
    cudaFuncSetAttribute(mma_lstm, cudaFuncAttributeMaxDynamicSharedMemorySize, GEMM_SMEM);

    const size_t hElems = (size_t)kM * kH;
    cudaMemsetAsync(c0, 0, hElems * 4);
    cudaMemsetAsync(c1, 0, hElems * 4);
    cudaMemsetAsync(h0h, 0, hElems * 2);
    cudaMemsetAsync(h0l, 0, hElems * 2);
    cudaMemsetAsync(h1h, 0, hElems * 2);
    cudaMemsetAsync(h1l, 0, hElems * 2);

    // weight prep
    transpose_f16_kernel<<<k4H / 8, 256>>>(Wi0, k4H, 1, Wi0T);
    transpose_f16_kernel<<<k4H / 8, 256>>>(Wh0, k4H, 1, Wh0T);
    transpose_f16_kernel<<<k4H / 8, 256>>>(Wi1, k4H, 1, Wi1T);
    transpose_f16_kernel<<<k4H / 8, 256>>>(Wh1, k4H, 1, Wh1T);
    transpose_f16_kernel<<<kH / 8, 256>>>(Wk, kH, 0, WkT);
    perm_bias_kernel<<<4, 256>>>(b0, bP0);
    perm_bias_kernel<<<4, 256>>>(b1, bP1);
    split_kernel<<<(kV * kH / 4 + 255) / 256, 256>>>(
        (const float4*)embed, (__half2*)embh, (__half2*)embl, kV * kH / 4);

    // G0 = embed @ Wi0 (gate-permuted)  [32000, 1024]
    mma_gemm<<<dim3(k4H / 128, kV / 128), 256, GEMM_SMEM>>>(
        kV, k4H, embh, embl, Wi0T, nullptr, G0);

    // LSTM: 8 timesteps, 2 layers; h buffers ping-pong (rb -> wb)
    for (int t = 0; t < kL; t++) {
        size_t rb = (size_t)(t & 1) * hElems, wb = (size_t)((t & 1) ^ 1) * hElems;
        mma_lstm<<<dim3(k4H / 128, kM / 128), 256, GEMM_SMEM>>>(
            1, h0h + rb, h0l + rb, Wh0T,
            nullptr, nullptr, nullptr,
            bP0, G0, data + t, kL,
            c0, h0h + wb, h0l + wb, nullptr);
        mma_lstm<<<dim3(k4H / 128, kM / 128), 256, GEMM_SMEM>>>(
            2, h0h + wb, h0l + wb, Wi1T,
            h1h + rb, h1l + rb, Wh1T,
            bP1, nullptr, nullptr, 0,
            c1, h1h + wb, h1l + wb, (t == kL - 1) ? se : nullptr);
    }
    // final h1 (and its fp16 split) is in buffer 0

    compute_ae_kernel<<<1, 256>>>(edge_table, Wa);

    for (int step = 0; step < kMaxSteps; step++) {
        mma_gemm<<<dim3(kH / 128, kM / 128), 256, GEMM_SMEM>>>(
            kM, kH, h1h, h1l, WkT, bk, keys);
        node_scores_kernel<<<kM / 8, 256>>>(keys, Wa);
        init_seg_kernel<<<kM / 256, 256>>>();
        cudaMemsetAsync(nw, 0, hElems * 4);
        edge_pass1<<<kB * kE / 256, 256>>>(src, dst, et, steps, ba, step);
        edge_pass2<<<kB * kE / 256, 256>>>(dst, steps, step);
        edge_pass3<<<kB * kE * 32 / 256, 256>>>(src, dst, et, steps, edge_table, step);
        masked_copy_kernel<<<kM * kH / 4 / 256, 256>>>(
            steps, step, (const float4*)nw, (float4*)se,
            (__half2*)h1h, (__half2*)h1l);
    }

    final_kernel<<<kB, 256>>>(se, exit_index, Wo, bo, out);
}

// round 5
// speedup vs baseline: 2.8874x; 1.3631x over previous
#include <cuda_runtime.h>
#include <cuda_fp16.h>
#include <math.h>
#include <stdint.h>

namespace {
constexpr int kB = 8, kN = 4096, kL = 8, kE = 16384, kH = 256;
constexpr int kV = 32000, kOV = 512, kMaxSteps = 6;
constexpr int kM = kB * kN;        // 32768
constexpr int k4H = 4 * kH;        // 1024
constexpr int TILE_B = 10240;      // 128 rows * 80 bytes (32 fp16 + pad)
constexpr int GEMM_SMEM = 4 * TILE_B;   // A/B double buffered
}

// ---------------- scratch ---------------------------------------------------
__device__ float g_G0[(size_t)kV * k4H];          // embed @ Wi0 (gate-permuted cols)
__device__ float g_c0[kM * kH], g_c1[kM * kH];
__device__ __half g_h0h[2][kM * kH];
__device__ __half g_h1h[2][kM * kH];              // buffer 0 doubles as se fp16
__device__ float g_se[kM * kH];
__device__ __half g_embh[(size_t)kV * kH];
__device__ __half g_Wi0T[k4H * kH], g_Wh0T[k4H * kH];
__device__ __half g_Wi1T[k4H * kH], g_Wh1T[k4H * kH];
__device__ __half g_WkT[kH * kH];
__device__ float g_bP0[k4H], g_bP1[k4H];
__device__ float g_new[kM * kH];
__device__ float g_keys[kM * kH];
__device__ float g_ak[kM], g_aq[kM], g_mx[kM], g_ss[kM];
__device__ float g_edge[kB * kE];
__device__ float g_ae[8];

// ---------------- PTX helpers ----------------------------------------------
__device__ __forceinline__ uint32_t smem_u32(const void* p) {
    uint32_t a;
    asm("{ .reg .u64 t; cvta.to.shared.u64 t, %1; cvt.u32.u64 %0, t; }"
        : "=r"(a) : "l"(p));
    return a;
}
__device__ __forceinline__ void cpasync16(uint32_t dst, const void* src) {
    asm volatile("cp.async.cg.shared.global [%0], [%1], 16;"
                 :: "r"(dst), "l"(src) : "memory");
}
__device__ __forceinline__ void cp_commit() {
    asm volatile("cp.async.commit_group;" ::: "memory");
}
template <int N>
__device__ __forceinline__ void cp_wait() {
    asm volatile("cp.async.wait_group %0;" :: "n"(N) : "memory");
}
__device__ __forceinline__ void ldsm4(uint32_t* r, uint32_t a) {
    asm volatile("ldmatrix.sync.aligned.m8n8.x4.shared.b16 {%0,%1,%2,%3}, [%4];"
                 : "=r"(r[0]), "=r"(r[1]), "=r"(r[2]), "=r"(r[3]) : "r"(a));
}
__device__ __forceinline__ void mma16816(float* d, const uint32_t* a, const uint32_t* b) {
    asm volatile(
        "mma.sync.aligned.m16n8k16.row.col.f32.f16.f16.f32 "
        "{%0,%1,%2,%3}, {%4,%5,%6,%7}, {%8,%9}, {%0,%1,%2,%3};"
        : "+f"(d[0]), "+f"(d[1]), "+f"(d[2]), "+f"(d[3])
        : "r"(a[0]), "r"(a[1]), "r"(a[2]), "r"(a[3]), "r"(b[0]), "r"(b[1]));
}
__device__ __forceinline__ float sigm(float x) { return 1.f / (1.f + expf(-x)); }

// ---------------- shared GEMM mainloop pieces --------------------------------
#define GEMM_PROLOGUE                                                            \
    extern __shared__ __align__(128) char smem[];                               \
    const int tid = threadIdx.x, wid = tid >> 5, lane = tid & 31;               \
    const int mBase = blockIdx.y * 128, nBase = blockIdx.x * 128;               \
    const int wM = (wid & 3) * 32, wN = (wid >> 2) * 64;                        \
    const uint32_t sbase = smem_u32(smem);                                      \
    float acc[2][8][4];                                                         \
    _Pragma("unroll") for (int i = 0; i < 2; i++)                               \
    _Pragma("unroll") for (int j = 0; j < 8; j++)                               \
    _Pragma("unroll") for (int k = 0; k < 4; k++) acc[i][j][k] = 0.f;

__device__ __forceinline__ void load_tiles(uint32_t sbase, int buf, int tid,
        const __half* __restrict__ Ap, const __half* __restrict__ Bp,
        int mBase, int nBase, int kt) {
    const uint32_t sA = sbase + (uint32_t)buf * (2 * TILE_B);
    const uint32_t sB = sA + TILE_B;
#pragma unroll
    for (int i = 0; i < 2; i++) {
        int idx = i * 256 + tid;
        int r = idx >> 2, cc4 = idx & 3;
        cpasync16(sA + r * 80 + cc4 * 16,
                  Ap + (size_t)(mBase + r) * 256 + kt + cc4 * 8);
        cpasync16(sB + r * 80 + cc4 * 16,
                  Bp + (size_t)(nBase + r) * 256 + kt + cc4 * 8);
    }
    cp_commit();
}

__device__ __forceinline__ void compute_tiles(uint32_t sbase, int buf,
        int wM, int wN, int lane, float acc[2][8][4]) {
    const uint32_t sA = sbase + (uint32_t)buf * (2 * TILE_B);
    const uint32_t sB = sA + TILE_B;
#pragma unroll
    for (int ks = 0; ks < 2; ks++) {
        uint32_t a[2][4];
#pragma unroll
        for (int mt = 0; mt < 2; mt++) {
            int row = wM + mt * 16 + (lane & 15);
            ldsm4(a[mt], sA + row * 80 + ((lane >> 4) * 16) + ks * 32);
        }
#pragma unroll
        for (int nt2 = 0; nt2 < 4; nt2++) {
            uint32_t b[4];
            int nrow = wN + nt2 * 16 + (lane & 7) + ((lane >> 4) << 3);
            ldsm4(b, sB + nrow * 80 + (((lane >> 3) & 1) * 16) + ks * 32);
            mma16816(acc[0][nt2 * 2 + 0], a[0], b + 0);
            mma16816(acc[0][nt2 * 2 + 1], a[0], b + 2);
            mma16816(acc[1][nt2 * 2 + 0], a[1], b + 0);
            mma16816(acc[1][nt2 * 2 + 1], a[1], b + 2);
        }
    }
}

// ---------------- generic 1-pass fp16 GEMM (G0 precompute, keys) -------------
// C[M,NTotal] = A[M,256] @ B[N,256]^T + bias; optional per-batch step skip.
__global__ void __launch_bounds__(256, 2) mma_gemm(
    int M, int NTotal,
    const __half* __restrict__ A, const __half* __restrict__ B,
    const float* __restrict__ bias, float* __restrict__ C,
    const int* __restrict__ steps, int step)
{
    if (steps && step >= steps[(blockIdx.y * 128) / kN]) return;
    GEMM_PROLOGUE
    load_tiles(sbase, 0, tid, A, B, mBase, nBase, 0);
    for (int c = 0; c < 7; ++c) {
        load_tiles(sbase, (c + 1) & 1, tid, A, B, mBase, nBase, (c + 1) * 32);
        cp_wait<1>();
        __syncthreads();
        compute_tiles(sbase, c & 1, wM, wN, lane, acc);
        __syncthreads();
    }
    cp_wait<0>();
    __syncthreads();
    compute_tiles(sbase, 1, wM, wN, lane, acc);

#pragma unroll
    for (int mt = 0; mt < 2; mt++) {
        int r0 = mBase + wM + mt * 16 + (lane >> 2);
        int r1 = r0 + 8;
#pragma unroll
        for (int nt = 0; nt < 8; nt++) {
            int n = nBase + wN + nt * 8 + (lane & 3) * 2;
            float2 v0 = make_float2(acc[mt][nt][0], acc[mt][nt][1]);
            float2 v1 = make_float2(acc[mt][nt][2], acc[mt][nt][3]);
            if (bias) {
                float2 bv = *(const float2*)(bias + n);
                v0.x += bv.x; v0.y += bv.y; v1.x += bv.x; v1.y += bv.y;
            }
            *(float2*)(C + (size_t)r0 * NTotal + n) = v0;
            *(float2*)(C + (size_t)r1 * NTotal + n) = v1;
        }
    }
}

// ---------------- fused LSTM GEMM + gates (1-pass fp16) -----------------------
// z = sum_pairs Ap @ Bp^T + biasP (+ G0[token] gather), gate-interleaved cols
// (col n -> gate n&3 of unit n>>2). LSTM cell applied in-epilogue.
__global__ void __launch_bounds__(256, 2) mma_lstm(
    int nPairs,
    const __half* __restrict__ A0, const __half* __restrict__ B0,
    const __half* __restrict__ A1, const __half* __restrict__ B1,
    const float* __restrict__ biasP,
    const float* __restrict__ G0, const int* __restrict__ tokIdx, int tokStride,
    float* __restrict__ c,
    __half* __restrict__ outh, float* __restrict__ seOut)
{
    GEMM_PROLOGUE
    const int nChunks = nPairs * 8;
    auto srcs = [&](int cc, const __half*& Ap, const __half*& Bp, int& kt) {
        int pair = cc >> 3;
        kt = (cc & 7) * 32;
        Ap = pair ? A1 : A0;
        Bp = pair ? B1 : B0;
    };
    {
        const __half *Ap, *Bp; int kt;
        srcs(0, Ap, Bp, kt);
        load_tiles(sbase, 0, tid, Ap, Bp, mBase, nBase, kt);
    }
    for (int cc = 0; cc < nChunks - 1; ++cc) {
        const __half *Ap, *Bp; int kt;
        srcs(cc + 1, Ap, Bp, kt);
        load_tiles(sbase, (cc + 1) & 1, tid, Ap, Bp, mBase, nBase, kt);
        cp_wait<1>();
        __syncthreads();
        compute_tiles(sbase, cc & 1, wM, wN, lane, acc);
        __syncthreads();
    }
    cp_wait<0>();
    __syncthreads();
    compute_tiles(sbase, (nChunks - 1) & 1, wM, wN, lane, acc);

    // ---- fused epilogue: bias + gather + LSTM cell ----
#pragma unroll
    for (int mt = 0; mt < 2; mt++) {
        int r0 = mBase + wM + mt * 16 + (lane >> 2);
        int r1 = r0 + 8;
        const float *g0 = nullptr, *g1 = nullptr;
        if (G0) {
            g0 = G0 + (size_t)tokIdx[(size_t)r0 * tokStride] * k4H;
            g1 = G0 + (size_t)tokIdx[(size_t)r1 * tokStride] * k4H;
        }
#pragma unroll
        for (int nt = 0; nt < 8; nt++) {
            int n = nBase + wN + nt * 8 + (lane & 3) * 2;
            float z0 = acc[mt][nt][0] + biasP[n];
            float z1 = acc[mt][nt][1] + biasP[n + 1];
            float z2 = acc[mt][nt][2] + biasP[n];
            float z3 = acc[mt][nt][3] + biasP[n + 1];
            if (g0) {
                z0 += g0[n]; z1 += g0[n + 1];
                z2 += g1[n]; z3 += g1[n + 1];
            }
            // lane pair (lane^1) exchange: even lanes keep row r0, odd row r1
            float e0 = __shfl_xor_sync(0xffffffffu, z0, 1);
            float e1 = __shfl_xor_sync(0xffffffffu, z1, 1);
            float e2 = __shfl_xor_sync(0xffffffffu, z2, 1);
            float e3 = __shfl_xor_sync(0xffffffffu, z3, 1);
            bool evn = (lane & 1) == 0;
            int row = evn ? r0 : r1;
            float zi = evn ? z0 : e2;
            float zf = evn ? z1 : e3;
            float zg = evn ? e0 : z2;
            float zo = evn ? e1 : z3;
            int uG = ((nBase + wN + nt * 8) >> 2) + ((lane & 3) >> 1);
            size_t idx = (size_t)row * kH + uG;
            float cn = sigm(zf) * c[idx] + sigm(zi) * tanhf(zg);
            c[idx] = cn;
            float hn = sigm(zo) * tanhf(cn);
            outh[idx] = __float2half(hn);
            if (seOut) seOut[idx] = hn;
        }
    }
}

// ---------------- consolidated weight prep ------------------------------------
// blocks 0..511: gate-permuted transposes of Wi0/Wh0/Wi1/Wh1 (128 blocks each)
// blocks 512..543: WkT plain transpose; blocks 544..551: bias permutes
__global__ void __launch_bounds__(256) prep_weights_kernel(
    const float* __restrict__ Wi0, const float* __restrict__ Wh0,
    const float* __restrict__ Wi1, const float* __restrict__ Wh1,
    const float* __restrict__ Wk,
    const float* __restrict__ b0, const float* __restrict__ b1,
    __half* __restrict__ Wi0T, __half* __restrict__ Wh0T,
    __half* __restrict__ Wi1T, __half* __restrict__ Wh1T,
    __half* __restrict__ WkT, float* __restrict__ bP0, float* __restrict__ bP1)
{
    int blk = blockIdx.x;
    if (blk < 512) {
        const float* W; __half* T;
        switch (blk >> 7) {
            case 0: W = Wi0; T = Wi0T; break;
            case 1: W = Wh0; T = Wh0T; break;
            case 2: W = Wi1; T = Wi1T; break;
            default: W = Wh1; T = Wh1T;
        }
        int n = (blk & 127) * 8 + (threadIdx.x >> 5);
        int lane = threadIdx.x & 31;
        int col = (n & 3) * kH + (n >> 2);
        for (int kk = lane; kk < kH; kk += 32)
            T[(size_t)n * kH + kk] = __float2half(W[(size_t)kk * k4H + col]);
    } else if (blk < 544) {
        int n = (blk - 512) * 8 + (threadIdx.x >> 5);
        int lane = threadIdx.x & 31;
        for (int kk = lane; kk < kH; kk += 32)
            WkT[(size_t)n * kH + kk] = __float2half(Wk[(size_t)kk * kH + n]);
    } else {
        int i = blk - 544;                       // 0..7
        const float* b = (i < 4) ? b0 : b1;
        float* bP = (i < 4) ? bP0 : bP1;
        int n = (i & 3) * 256 + threadIdx.x;
        bP[n] = b[(n & 3) * kH + (n >> 2)];
    }
}

// fp32 -> fp16 convert (embed table)
__global__ void __launch_bounds__(256) convert_embed_kernel(
    const float4* __restrict__ x, __half2* __restrict__ h2, int n4)
{
    int i = blockIdx.x * 256 + threadIdx.x;
    if (i >= n4) return;
    float4 v = x[i];
    h2[i * 2 + 0] = __halves2half2(__float2half(v.x), __float2half(v.y));
    h2[i * 2 + 1] = __halves2half2(__float2half(v.z), __float2half(v.w));
}

// ---------------- GAT helpers -------------------------------------------------
__global__ void compute_ae_kernel(const float* __restrict__ edge_table,
                                  const float* __restrict__ Wa)
{
    int w = threadIdx.x >> 5, lane = threadIdx.x & 31;
    if (w >= 6) return;
    float s = 0.f;
    for (int hh = lane; hh < kH; hh += 32) s += edge_table[w * kH + hh] * Wa[hh];
#pragma unroll
    for (int o = 16; o; o >>= 1) s += __shfl_down_sync(0xffffffffu, s, o);
    if (!lane) g_ae[w] = s;
}

__global__ void __launch_bounds__(256) node_scores_kernel(
    const float* __restrict__ keys, const float* __restrict__ Wa,
    const int* __restrict__ steps, int step)
{
    if (step >= steps[(blockIdx.x * 8) / kN]) return;
    __shared__ float sWa[2 * kH];
    int tid = threadIdx.x;
    for (int i = tid; i < 2 * kH; i += 256) sWa[i] = Wa[i];
    __syncthreads();
    int node = (blockIdx.x * 256 + tid) >> 5;
    int lane = tid & 31;
    const float* kr = keys + (size_t)node * kH;
    float s1 = 0.f, s2 = 0.f;
    for (int hh = lane; hh < kH; hh += 32) {
        float kv = kr[hh];
        s1 += kv * sWa[hh];
        s2 += kv * sWa[kH + hh];
    }
#pragma unroll
    for (int o = 16; o; o >>= 1) {
        s1 += __shfl_down_sync(0xffffffffu, s1, o);
        s2 += __shfl_down_sync(0xffffffffu, s2, o);
    }
    if (!lane) { g_ak[node] = s1; g_aq[node] = s2; }
}

__global__ void init_seg_kernel()
{
    int i = blockIdx.x * 256 + threadIdx.x;
    g_mx[i] = -INFINITY;
    g_ss[i] = 0.f;
}

__device__ __forceinline__ float atomicMaxF(float* addr, float val)
{
    if (val >= 0.f)
        return __int_as_float(atomicMax((int*)addr, __float_as_int(val)));
    else
        return __uint_as_float(atomicMin((unsigned int*)addr, __float_as_uint(val)));
}

__global__ void __launch_bounds__(256) edge_pass1(
    const int* __restrict__ src, const int* __restrict__ dst,
    const int* __restrict__ et, const int* __restrict__ steps,
    const float* __restrict__ ba, int step)
{
    int e = blockIdx.x * 256 + threadIdx.x;
    int b = e / kE;
    if (step >= steps[b]) return;
    int d = dst[e];
    float lg = g_ak[b * kN + src[e]] + g_ae[et[e]] + g_aq[b * kN + d] + ba[0];
    lg = fmaxf(0.2f * lg, lg);
    g_edge[e] = lg;
    atomicMaxF(&g_mx[b * kN + d], lg);
}

__global__ void __launch_bounds__(256) edge_pass2(
    const int* __restrict__ dst, const int* __restrict__ steps, int step)
{
    int e = blockIdx.x * 256 + threadIdx.x;
    int b = e / kE;
    if (step >= steps[b]) return;
    int d = dst[e];
    float ex = expf(g_edge[e] - g_mx[b * kN + d]);
    g_edge[e] = ex;
    atomicAdd(&g_ss[b * kN + d], ex);
}

__global__ void __launch_bounds__(256) edge_pass3(
    const int* __restrict__ src, const int* __restrict__ dst,
    const int* __restrict__ et, const int* __restrict__ steps,
    const float* __restrict__ edge_table, int step)
{
    int gid = blockIdx.x * 256 + threadIdx.x;
    int e = gid >> 5, lane = gid & 31;
    int b = e / kE;
    if (step >= steps[b]) return;
    int s = src[e], d = dst[e], t = et[e];
    float w = g_edge[e] / g_ss[b * kN + d];
    const float* kr = g_keys + (size_t)(b * kN + s) * kH;
    const float* er = edge_table + t * kH;
    float* orow = g_new + (size_t)(b * kN + d) * kH;
    for (int hh = lane; hh < kH; hh += 32)
        atomicAdd(&orow[hh], (kr[hh] + er[hh]) * w);
}

// masked copy: se(fp32) and se fp16 updated together
__global__ void __launch_bounds__(256) masked_copy_kernel(
    const int* __restrict__ steps, int step,
    const float4* __restrict__ nw, float4* __restrict__ se,
    __half2* __restrict__ seh)
{
    int i = blockIdx.x * 256 + threadIdx.x;
    int b = i / (kN * kH / 4);
    if (step >= steps[b]) return;
    float4 v = nw[i];
    se[i] = v;
    seh[i * 2 + 0] = __halves2half2(__float2half(v.x), __float2half(v.y));
    seh[i * 2 + 1] = __halves2half2(__float2half(v.z), __float2half(v.w));
}

// ---------------- final gather + dense ---------------------------------------
__global__ void __launch_bounds__(256) final_kernel(
    const float* __restrict__ se, const int* __restrict__ exit_index,
    const float* __restrict__ Wo, const float* __restrict__ bo,
    float* __restrict__ out)
{
    __shared__ float fin[kH];
    int b = blockIdx.x, tid = threadIdx.x;
    const float* row = se + ((size_t)b * kN + exit_index[b]) * kH;
    if (tid < kH) fin[tid] = row[tid];
    __syncthreads();
    for (int j = tid; j < kOV; j += 256) {
        float s = bo[j];
        for (int hh = 0; hh < kH; hh++) s += fin[hh] * Wo[(size_t)hh * kOV + j];
        out[b * kOV + j] = s;
    }
}

// ---------------- driver ------------------------------------------------------
extern "C" void kernel_launch(void* const* d_in, const int* in_sizes, int n_in,
                              void* d_out, int out_size)
{
    const int*   data       = (const int*)d_in[0];
    const int*   src        = (const int*)d_in[1];
    const int*   dst        = (const int*)d_in[2];
    const int*   et         = (const int*)d_in[3];
    const int*   steps      = (const int*)d_in[4];
    const int*   exit_index = (const int*)d_in[5];
    const float* embed      = (const float*)d_in[6];
    const float* Wi0        = (const float*)d_in[7];
    const float* Wh0        = (const float*)d_in[8];
    const float* b0         = (const float*)d_in[9];
    const float* Wi1        = (const float*)d_in[10];
    const float* Wh1        = (const float*)d_in[11];
    const float* b1         = (const float*)d_in[12];
    const float* Wk         = (const float*)d_in[13];
    const float* bk         = (const float*)d_in[14];
    const float* Wa         = (const float*)d_in[15];
    const float* ba         = (const float*)d_in[16];
    const float* edge_table = (const float*)d_in[17];
    const float* Wo         = (const float*)d_in[18];
    const float* bo         = (const float*)d_in[19];
    float* out = (float*)d_out;

    float *G0, *c0, *c1, *se, *nw, *keys, *bP0, *bP1;
    __half *h0h, *h1h, *embh;
    __half *Wi0T, *Wh0T, *Wi1T, *Wh1T, *WkT;
    cudaGetSymbolAddress((void**)&G0,   g_G0);
    cudaGetSymbolAddress((void**)&c0,   g_c0);
    cudaGetSymbolAddress((void**)&c1,   g_c1);
    cudaGetSymbolAddress((void**)&se,   g_se);
    cudaGetSymbolAddress((void**)&nw,   g_new);
    cudaGetSymbolAddress((void**)&keys, g_keys);
    cudaGetSymbolAddress((void**)&h0h,  g_h0h);
    cudaGetSymbolAddress((void**)&h1h,  g_h1h);
    cudaGetSymbolAddress((void**)&embh, g_embh);
    cudaGetSymbolAddress((void**)&Wi0T, g_Wi0T);
    cudaGetSymbolAddress((void**)&Wh0T, g_Wh0T);
    cudaGetSymbolAddress((void**)&Wi1T, g_Wi1T);
    cudaGetSymbolAddress((void**)&Wh1T, g_Wh1T);
    cudaGetSymbolAddress((void**)&WkT,  g_WkT);
    cudaGetSymbolAddress((void**)&bP0,  g_bP0);
    cudaGetSymbolAddress((void**)&bP1,  g_bP1);

    cudaFuncSetAttribute(mma_gemm, cudaFuncAttributeMaxDynamicSharedMemorySize, GEMM_SMEM);
    cudaFuncSetAttribute(mma_lstm, cudaFuncAttributeMaxDynamicSharedMemorySize, GEMM_SMEM);

    const size_t hElems = (size_t)kM * kH;
    cudaMemsetAsync(c0, 0, hElems * 4);
    cudaMemsetAsync(c1, 0, hElems * 4);
    cudaMemsetAsync(h0h, 0, hElems * 2);   // buffer 0 only
    cudaMemsetAsync(h1h, 0, hElems * 2);

    prep_weights_kernel<<<552, 256>>>(Wi0, Wh0, Wi1, Wh1, Wk, b0, b1,
                                      Wi0T, Wh0T, Wi1T, Wh1T, WkT, bP0, bP1);
    convert_embed_kernel<<<(kV * kH / 4 + 255) / 256, 256>>>(
        (const float4*)embed, (__half2*)embh, kV * kH / 4);

    // G0 = embed @ Wi0 (gate-permuted)  [32000, 1024]
    mma_gemm<<<dim3(k4H / 128, kV / 128), 256, GEMM_SMEM>>>(
        kV, k4H, embh, Wi0T, nullptr, G0, nullptr, 0);

    // LSTM: 8 timesteps, 2 layers; h buffers ping-pong (rb -> wb)
    for (int t = 0; t < kL; t++) {
        size_t rb = (size_t)(t & 1) * hElems, wb = (size_t)((t & 1) ^ 1) * hElems;
        mma_lstm<<<dim3(k4H / 128, kM / 128), 256, GEMM_SMEM>>>(
            1, h0h + rb, Wh0T, nullptr, nullptr,
            bP0, G0, data + t, kL,
            c0, h0h + wb, nullptr);
        mma_lstm<<<dim3(k4H / 128, kM / 128), 256, GEMM_SMEM>>>(
            2, h0h + wb, Wi1T, h1h + rb, Wh1T,
            bP1, nullptr, nullptr, 0,
            c1, h1h + wb, (t == kL - 1) ? se : nullptr);
    }
    // final h1 fp16 is in buffer 0 (t=7 writes wb=0); se fp32 also written

    compute_ae_kernel<<<1, 256>>>(edge_table, Wa);

    for (int step = 0; step < kMaxSteps; step++) {
        mma_gemm<<<dim3(kH / 128, kM / 128), 256, GEMM_SMEM>>>(
            kM, kH, h1h, WkT, bk, keys, steps, step);
        node_scores_kernel<<<kM / 8, 256>>>(keys, Wa, steps, step);
        init_seg_kernel<<<kM / 256, 256>>>();
        cudaMemsetAsync(nw, 0, hElems * 4);
        edge_pass1<<<kB * kE / 256, 256>>>(src, dst, et, steps, ba, step);
        edge_pass2<<<kB * kE / 256, 256>>>(dst, steps, step);
        edge_pass3<<<kB * kE * 32 / 256, 256>>>(src, dst, et, steps, edge_table, step);
        masked_copy_kernel<<<kM * kH / 4 / 256, 256>>>(
            steps, step, (const float4*)nw, (float4*)se, (__half2*)h1h);
    }

    final_kernel<<<kB, 256>>>(se, exit_index, Wo, bo, out);
}

// round 6
// speedup vs baseline: 2.9800x; 1.0321x over previous
#include <cuda_runtime.h>
#include <cuda_fp16.h>
#include <math.h>
#include <stdint.h>

namespace {
constexpr int kB = 8, kN = 4096, kL = 8, kE = 16384, kH = 256;
constexpr int kV = 32000, kOV = 512, kMaxSteps = 6;
constexpr int kM = kB * kN;        // 32768
constexpr int k4H = 4 * kH;        // 1024
constexpr int STAGES = 4;
constexpr int TILE_B = 10240;      // 128 rows * 80 bytes (32 fp16 + pad)
constexpr int GEMM_SMEM = 2 * STAGES * TILE_B;   // 81920
}

// ---------------- scratch ---------------------------------------------------
__device__ float g_G0[(size_t)kV * k4H];          // embed @ Wi0 (gate-permuted cols)
__device__ float g_c0[kM * kH], g_c1[kM * kH];
__device__ __half g_h0h[2][kM * kH];
__device__ __half g_h1h[2][kM * kH];              // buffer 0 doubles as se fp16
__device__ float g_se[kM * kH];
__device__ __half g_embh[(size_t)kV * kH];
__device__ __half g_Wi0T[k4H * kH], g_Wh0T[k4H * kH];
__device__ __half g_Wi1T[k4H * kH], g_Wh1T[k4H * kH];
__device__ __half g_WkT[kH * kH];
__device__ float g_bP0[k4H], g_bP1[k4H];
__device__ float g_new[kM * kH];
__device__ float g_keys[kM * kH];
__device__ float g_ak[kM], g_aq[kM], g_mx[kM], g_ss[kM];
__device__ float g_edge[kB * kE];
__device__ float g_ae[8];

// ---------------- PTX helpers ----------------------------------------------
__device__ __forceinline__ uint32_t smem_u32(const void* p) {
    uint32_t a;
    asm("{ .reg .u64 t; cvta.to.shared.u64 t, %1; cvt.u32.u64 %0, t; }"
        : "=r"(a) : "l"(p));
    return a;
}
__device__ __forceinline__ void cpasync16(uint32_t dst, const void* src) {
    asm volatile("cp.async.cg.shared.global [%0], [%1], 16;"
                 :: "r"(dst), "l"(src) : "memory");
}
__device__ __forceinline__ void cp_commit() {
    asm volatile("cp.async.commit_group;" ::: "memory");
}
template <int N>
__device__ __forceinline__ void cp_wait() {
    asm volatile("cp.async.wait_group %0;" :: "n"(N) : "memory");
}
__device__ __forceinline__ void ldsm4(uint32_t* r, uint32_t a) {
    asm volatile("ldmatrix.sync.aligned.m8n8.x4.shared.b16 {%0,%1,%2,%3}, [%4];"
                 : "=r"(r[0]), "=r"(r[1]), "=r"(r[2]), "=r"(r[3]) : "r"(a));
}
__device__ __forceinline__ void mma16816(float* d, const uint32_t* a, const uint32_t* b) {
    asm volatile(
        "mma.sync.aligned.m16n8k16.row.col.f32.f16.f16.f32 "
        "{%0,%1,%2,%3}, {%4,%5,%6,%7}, {%8,%9}, {%0,%1,%2,%3};"
        : "+f"(d[0]), "+f"(d[1]), "+f"(d[2]), "+f"(d[3])
        : "r"(a[0]), "r"(a[1]), "r"(a[2]), "r"(a[3]), "r"(b[0]), "r"(b[1]));
}
__device__ __forceinline__ float sigm(float x) { return 1.f / (1.f + expf(-x)); }

// ---------------- shared GEMM mainloop pieces --------------------------------
#define GEMM_PROLOGUE                                                            \
    extern __shared__ __align__(128) char smem[];                               \
    const int tid = threadIdx.x, wid = tid >> 5, lane = tid & 31;               \
    const int mBase = blockIdx.y * 128, nBase = blockIdx.x * 128;               \
    const int wM = (wid & 3) * 32, wN = (wid >> 2) * 64;                        \
    const uint32_t sbase = smem_u32(smem);                                      \
    float acc[2][8][4];                                                         \
    _Pragma("unroll") for (int i = 0; i < 2; i++)                               \
    _Pragma("unroll") for (int j = 0; j < 8; j++)                               \
    _Pragma("unroll") for (int k = 0; k < 4; k++) acc[i][j][k] = 0.f;

__device__ __forceinline__ void load_tiles(uint32_t sbase, int buf, int tid,
        const __half* __restrict__ Ap, const __half* __restrict__ Bp,
        int mBase, int nBase, int kt) {
    const uint32_t sA = sbase + (uint32_t)buf * (2 * TILE_B);
    const uint32_t sB = sA + TILE_B;
#pragma unroll
    for (int i = 0; i < 2; i++) {
        int idx = i * 256 + tid;
        int r = idx >> 2, cc4 = idx & 3;
        cpasync16(sA + r * 80 + cc4 * 16,
                  Ap + (size_t)(mBase + r) * 256 + kt + cc4 * 8);
        cpasync16(sB + r * 80 + cc4 * 16,
                  Bp + (size_t)(nBase + r) * 256 + kt + cc4 * 8);
    }
    cp_commit();
}

__device__ __forceinline__ void compute_tiles(uint32_t sbase, int buf,
        int wM, int wN, int lane, float acc[2][8][4]) {
    const uint32_t sA = sbase + (uint32_t)buf * (2 * TILE_B);
    const uint32_t sB = sA + TILE_B;
#pragma unroll
    for (int ks = 0; ks < 2; ks++) {
        uint32_t a[2][4];
#pragma unroll
        for (int mt = 0; mt < 2; mt++) {
            int row = wM + mt * 16 + (lane & 15);
            ldsm4(a[mt], sA + row * 80 + ((lane >> 4) * 16) + ks * 32);
        }
#pragma unroll
        for (int nt2 = 0; nt2 < 4; nt2++) {
            uint32_t b[4];
            int nrow = wN + nt2 * 16 + (lane & 7) + ((lane >> 4) << 3);
            ldsm4(b, sB + nrow * 80 + (((lane >> 3) & 1) * 16) + ks * 32);
            mma16816(acc[0][nt2 * 2 + 0], a[0], b + 0);
            mma16816(acc[0][nt2 * 2 + 1], a[0], b + 2);
            mma16816(acc[1][nt2 * 2 + 0], a[1], b + 0);
            mma16816(acc[1][nt2 * 2 + 1], a[1], b + 2);
        }
    }
}

// 4-stage pipeline, one __syncthreads per chunk. srcs(c, A, B, kt) yields the
// global sources for chunk c; exactly one commit_group per iteration (real or
// empty) keeps wait_group accounting exact at the tail.
#define GEMM_MAINLOOP(NCHUNKS, SRCS)                                            \
    {                                                                            \
        const __half *Ap_, *Bp_; int kt_;                                        \
        _Pragma("unroll") for (int s = 0; s < STAGES - 1; s++) {                 \
            if (s < (NCHUNKS)) { SRCS(s, Ap_, Bp_, kt_);                         \
                load_tiles(sbase, s, tid, Ap_, Bp_, mBase, nBase, kt_); }        \
            else cp_commit();                                                    \
        }                                                                        \
        for (int c = 0; c < (NCHUNKS); ++c) {                                   \
            cp_wait<STAGES - 2>();                                               \
            __syncthreads();                                                     \
            int pre = c + STAGES - 1;                                            \
            if (pre < (NCHUNKS)) { SRCS(pre, Ap_, Bp_, kt_);                     \
                load_tiles(sbase, pre & (STAGES - 1), tid, Ap_, Bp_,             \
                           mBase, nBase, kt_); }                                 \
            else cp_commit();                                                    \
            compute_tiles(sbase, c & (STAGES - 1), wM, wN, lane, acc);           \
        }                                                                        \
    }

// ---------------- generic 1-pass fp16 GEMM (G0 precompute, keys) -------------
// C[M,NTotal] = A[M,256] @ B[N,256]^T + bias; optional per-batch step skip;
// optional fused partial node-score dots (atomicAdd into ak/aq).
__global__ void __launch_bounds__(256, 2) mma_gemm(
    int M, int NTotal,
    const __half* __restrict__ A, const __half* __restrict__ B,
    const float* __restrict__ bias, float* __restrict__ C,
    const int* __restrict__ steps, int step, const float* __restrict__ Wa)
{
    if (steps && step >= steps[(blockIdx.y * 128) / kN]) return;
    GEMM_PROLOGUE
#define SRCS_PLAIN(c, Ap, Bp, kt) { Ap = A; Bp = B; kt = (c) * 32; }
    GEMM_MAINLOOP(8, SRCS_PLAIN)
#undef SRCS_PLAIN

#pragma unroll
    for (int mt = 0; mt < 2; mt++) {
        int r0 = mBase + wM + mt * 16 + (lane >> 2);
        int r1 = r0 + 8;
        float ak0 = 0.f, aq0 = 0.f, ak1 = 0.f, aq1 = 0.f;
#pragma unroll
        for (int nt = 0; nt < 8; nt++) {
            int n = nBase + wN + nt * 8 + (lane & 3) * 2;
            float2 v0 = make_float2(acc[mt][nt][0], acc[mt][nt][1]);
            float2 v1 = make_float2(acc[mt][nt][2], acc[mt][nt][3]);
            if (bias) {
                float2 bv = *(const float2*)(bias + n);
                v0.x += bv.x; v0.y += bv.y; v1.x += bv.x; v1.y += bv.y;
            }
            *(float2*)(C + (size_t)r0 * NTotal + n) = v0;
            *(float2*)(C + (size_t)r1 * NTotal + n) = v1;
            if (Wa) {
                float2 w1 = *(const float2*)(Wa + n);
                float2 w2 = *(const float2*)(Wa + kH + n);
                ak0 += v0.x * w1.x + v0.y * w1.y;
                aq0 += v0.x * w2.x + v0.y * w2.y;
                ak1 += v1.x * w1.x + v1.y * w1.y;
                aq1 += v1.x * w2.x + v1.y * w2.y;
            }
        }
        if (Wa) {
            // reduce over the quad (lane&3): each quad holds rows r0, r1
#pragma unroll
            for (int o = 1; o <= 2; o <<= 1) {
                ak0 += __shfl_xor_sync(0xffffffffu, ak0, o);
                aq0 += __shfl_xor_sync(0xffffffffu, aq0, o);
                ak1 += __shfl_xor_sync(0xffffffffu, ak1, o);
                aq1 += __shfl_xor_sync(0xffffffffu, aq1, o);
            }
            if ((lane & 3) == 0) {
                atomicAdd(&g_ak[r0], ak0);
                atomicAdd(&g_aq[r0], aq0);
                atomicAdd(&g_ak[r1], ak1);
                atomicAdd(&g_aq[r1], aq1);
            }
        }
    }
}

// ---------------- fused LSTM GEMM + gates (1-pass fp16) -----------------------
// z = sum_pairs Ap @ Bp^T + biasP (+ G0[token] gather), gate-interleaved cols
// (col n -> gate n&3 of unit n>>2). LSTM cell applied in-epilogue.
__global__ void __launch_bounds__(256, 2) mma_lstm(
    int nPairs,
    const __half* __restrict__ A0, const __half* __restrict__ B0,
    const __half* __restrict__ A1, const __half* __restrict__ B1,
    const float* __restrict__ biasP,
    const float* __restrict__ G0, const int* __restrict__ tokIdx, int tokStride,
    float* __restrict__ c,
    __half* __restrict__ outh, float* __restrict__ seOut)
{
    GEMM_PROLOGUE
    const int nChunks = nPairs * 8;
#define SRCS_LSTM(cc, Ap, Bp, kt) { int pair_ = (cc) >> 3;                      \
        kt = ((cc) & 7) * 32;                                                    \
        Ap = pair_ ? A1 : A0; Bp = pair_ ? B1 : B0; }
    GEMM_MAINLOOP(nChunks, SRCS_LSTM)
#undef SRCS_LSTM

    // ---- fused epilogue: bias + gather + LSTM cell ----
#pragma unroll
    for (int mt = 0; mt < 2; mt++) {
        int r0 = mBase + wM + mt * 16 + (lane >> 2);
        int r1 = r0 + 8;
        const float *g0 = nullptr, *g1 = nullptr;
        if (G0) {
            g0 = G0 + (size_t)tokIdx[(size_t)r0 * tokStride] * k4H;
            g1 = G0 + (size_t)tokIdx[(size_t)r1 * tokStride] * k4H;
        }
#pragma unroll
        for (int nt = 0; nt < 8; nt++) {
            int n = nBase + wN + nt * 8 + (lane & 3) * 2;
            float z0 = acc[mt][nt][0] + biasP[n];
            float z1 = acc[mt][nt][1] + biasP[n + 1];
            float z2 = acc[mt][nt][2] + biasP[n];
            float z3 = acc[mt][nt][3] + biasP[n + 1];
            if (g0) {
                z0 += g0[n]; z1 += g0[n + 1];
                z2 += g1[n]; z3 += g1[n + 1];
            }
            // lane pair (lane^1) exchange: even lanes keep row r0, odd row r1
            float e0 = __shfl_xor_sync(0xffffffffu, z0, 1);
            float e1 = __shfl_xor_sync(0xffffffffu, z1, 1);
            float e2 = __shfl_xor_sync(0xffffffffu, z2, 1);
            float e3 = __shfl_xor_sync(0xffffffffu, z3, 1);
            bool evn = (lane & 1) == 0;
            int row = evn ? r0 : r1;
            float zi = evn ? z0 : e2;
            float zf = evn ? z1 : e3;
            float zg = evn ? e0 : z2;
            float zo = evn ? e1 : z3;
            int uG = ((nBase + wN + nt * 8) >> 2) + ((lane & 3) >> 1);
            size_t idx = (size_t)row * kH + uG;
            float cn = sigm(zf) * c[idx] + sigm(zi) * tanhf(zg);
            c[idx] = cn;
            float hn = sigm(zo) * tanhf(cn);
            outh[idx] = __float2half(hn);
            if (seOut) seOut[idx] = hn;
        }
    }
}

// ---------------- consolidated weight prep ------------------------------------
__global__ void __launch_bounds__(256) prep_weights_kernel(
    const float* __restrict__ Wi0, const float* __restrict__ Wh0,
    const float* __restrict__ Wi1, const float* __restrict__ Wh1,
    const float* __restrict__ Wk,
    const float* __restrict__ b0, const float* __restrict__ b1,
    __half* __restrict__ Wi0T, __half* __restrict__ Wh0T,
    __half* __restrict__ Wi1T, __half* __restrict__ Wh1T,
    __half* __restrict__ WkT, float* __restrict__ bP0, float* __restrict__ bP1)
{
    int blk = blockIdx.x;
    if (blk < 512) {
        const float* W; __half* T;
        switch (blk >> 7) {
            case 0: W = Wi0; T = Wi0T; break;
            case 1: W = Wh0; T = Wh0T; break;
            case 2: W = Wi1; T = Wi1T; break;
            default: W = Wh1; T = Wh1T;
        }
        int n = (blk & 127) * 8 + (threadIdx.x >> 5);
        int lane = threadIdx.x & 31;
        int col = (n & 3) * kH + (n >> 2);
        for (int kk = lane; kk < kH; kk += 32)
            T[(size_t)n * kH + kk] = __float2half(W[(size_t)kk * k4H + col]);
    } else if (blk < 544) {
        int n = (blk - 512) * 8 + (threadIdx.x >> 5);
        int lane = threadIdx.x & 31;
        for (int kk = lane; kk < kH; kk += 32)
            WkT[(size_t)n * kH + kk] = __float2half(Wk[(size_t)kk * kH + n]);
    } else {
        int i = blk - 544;                       // 0..7
        const float* b = (i < 4) ? b0 : b1;
        float* bP = (i < 4) ? bP0 : bP1;
        int n = (i & 3) * 256 + threadIdx.x;
        bP[n] = b[(n & 3) * kH + (n >> 2)];
    }
}

__global__ void __launch_bounds__(256) convert_embed_kernel(
    const float4* __restrict__ x, __half2* __restrict__ h2, int n4)
{
    int i = blockIdx.x * 256 + threadIdx.x;
    if (i >= n4) return;
    float4 v = x[i];
    h2[i * 2 + 0] = __halves2half2(__float2half(v.x), __float2half(v.y));
    h2[i * 2 + 1] = __halves2half2(__float2half(v.z), __float2half(v.w));
}

// ---------------- GAT helpers -------------------------------------------------
__global__ void compute_ae_kernel(const float* __restrict__ edge_table,
                                  const float* __restrict__ Wa)
{
    int w = threadIdx.x >> 5, lane = threadIdx.x & 31;
    if (w >= 6) return;
    float s = 0.f;
    for (int hh = lane; hh < kH; hh += 32) s += edge_table[w * kH + hh] * Wa[hh];
#pragma unroll
    for (int o = 16; o; o >>= 1) s += __shfl_down_sync(0xffffffffu, s, o);
    if (!lane) g_ae[w] = s;
}

__global__ void init_seg_kernel()
{
    int i = blockIdx.x * 256 + threadIdx.x;
    g_mx[i] = -INFINITY;
    g_ss[i] = 0.f;
    g_ak[i] = 0.f;
    g_aq[i] = 0.f;
}

__device__ __forceinline__ float atomicMaxF(float* addr, float val)
{
    if (val >= 0.f)
        return __int_as_float(atomicMax((int*)addr, __float_as_int(val)));
    else
        return __uint_as_float(atomicMin((unsigned int*)addr, __float_as_uint(val)));
}

__global__ void __launch_bounds__(256) edge_pass1(
    const int* __restrict__ src, const int* __restrict__ dst,
    const int* __restrict__ et, const int* __restrict__ steps,
    const float* __restrict__ ba, int step)
{
    int e = blockIdx.x * 256 + threadIdx.x;
    int b = e / kE;
    if (step >= steps[b]) return;
    int d = dst[e];
    float lg = g_ak[b * kN + src[e]] + g_ae[et[e]] + g_aq[b * kN + d] + ba[0];
    lg = fmaxf(0.2f * lg, lg);
    g_edge[e] = lg;
    atomicMaxF(&g_mx[b * kN + d], lg);
}

__global__ void __launch_bounds__(256) edge_pass2(
    const int* __restrict__ dst, const int* __restrict__ steps, int step)
{
    int e = blockIdx.x * 256 + threadIdx.x;
    int b = e / kE;
    if (step >= steps[b]) return;
    int d = dst[e];
    float ex = expf(g_edge[e] - g_mx[b * kN + d]);
    g_edge[e] = ex;
    atomicAdd(&g_ss[b * kN + d], ex);
}

__global__ void __launch_bounds__(256) edge_pass3(
    const int* __restrict__ src, const int* __restrict__ dst,
    const int* __restrict__ et, const int* __restrict__ steps,
    const float* __restrict__ edge_table, int step)
{
    int gid = blockIdx.x * 256 + threadIdx.x;
    int e = gid >> 5, lane = gid & 31;
    int b = e / kE;
    if (step >= steps[b]) return;
    int s = src[e], d = dst[e], t = et[e];
    float w = g_edge[e] / g_ss[b * kN + d];
    const float* kr = g_keys + (size_t)(b * kN + s) * kH;
    const float* er = edge_table + t * kH;
    float* orow = g_new + (size_t)(b * kN + d) * kH;
    for (int hh = lane; hh < kH; hh += 32)
        atomicAdd(&orow[hh], (kr[hh] + er[hh]) * w);
}

// masked copy: se(fp32) and se fp16 updated together
__global__ void __launch_bounds__(256) masked_copy_kernel(
    const int* __restrict__ steps, int step,
    const float4* __restrict__ nw, float4* __restrict__ se,
    __half2* __restrict__ seh)
{
    int i = blockIdx.x * 256 + threadIdx.x;
    int b = i / (kN * kH / 4);
    if (step >= steps[b]) return;
    float4 v = nw[i];
    se[i] = v;
    seh[i * 2 + 0] = __halves2half2(__float2half(v.x), __float2half(v.y));
    seh[i * 2 + 1] = __halves2half2(__float2half(v.z), __float2half(v.w));
}

// ---------------- final gather + dense ---------------------------------------
__global__ void __launch_bounds__(256) final_kernel(
    const float* __restrict__ se, const int* __restrict__ exit_index,
    const float* __restrict__ Wo, const float* __restrict__ bo,
    float* __restrict__ out)
{
    __shared__ float fin[kH];
    int b = blockIdx.x, tid = threadIdx.x;
    const float* row = se + ((size_t)b * kN + exit_index[b]) * kH;
    if (tid < kH) fin[tid] = row[tid];
    __syncthreads();
    for (int j = tid; j < kOV; j += 256) {
        float s = bo[j];
        for (int hh = 0; hh < kH; hh++) s += fin[hh] * Wo[(size_t)hh * kOV + j];
        out[b * kOV + j] = s;
    }
}

// ---------------- driver ------------------------------------------------------
extern "C" void kernel_launch(void* const* d_in, const int* in_sizes, int n_in,
                              void* d_out, int out_size)
{
    const int*   data       = (const int*)d_in[0];
    const int*   src        = (const int*)d_in[1];
    const int*   dst        = (const int*)d_in[2];
    const int*   et         = (const int*)d_in[3];
    const int*   steps      = (const int*)d_in[4];
    const int*   exit_index = (const int*)d_in[5];
    const float* embed      = (const float*)d_in[6];
    const float* Wi0        = (const float*)d_in[7];
    const float* Wh0        = (const float*)d_in[8];
    const float* b0         = (const float*)d_in[9];
    const float* Wi1        = (const float*)d_in[10];
    const float* Wh1        = (const float*)d_in[11];
    const float* b1         = (const float*)d_in[12];
    const float* Wk         = (const float*)d_in[13];
    const float* bk         = (const float*)d_in[14];
    const float* Wa         = (const float*)d_in[15];
    const float* ba         = (const float*)d_in[16];
    const float* edge_table = (const float*)d_in[17];
    const float* Wo         = (const float*)d_in[18];
    const float* bo         = (const float*)d_in[19];
    float* out = (float*)d_out;

    float *G0, *c0, *c1, *se, *nw, *keys, *bP0, *bP1;
    __half *h0h, *h1h, *embh;
    __half *Wi0T, *Wh0T, *Wi1T, *Wh1T, *WkT;
    cudaGetSymbolAddress((void**)&G0,   g_G0);
    cudaGetSymbolAddress((void**)&c0,   g_c0);
    cudaGetSymbolAddress((void**)&c1,   g_c1);
    cudaGetSymbolAddress((void**)&se,   g_se);
    cudaGetSymbolAddress((void**)&nw,   g_new);
    cudaGetSymbolAddress((void**)&keys, g_keys);
    cudaGetSymbolAddress((void**)&h0h,  g_h0h);
    cudaGetSymbolAddress((void**)&h1h,  g_h1h);
    cudaGetSymbolAddress((void**)&embh, g_embh);
    cudaGetSymbolAddress((void**)&Wi0T, g_Wi0T);
    cudaGetSymbolAddress((void**)&Wh0T, g_Wh0T);
    cudaGetSymbolAddress((void**)&Wi1T, g_Wi1T);
    cudaGetSymbolAddress((void**)&Wh1T, g_Wh1T);
    cudaGetSymbolAddress((void**)&WkT,  g_WkT);
    cudaGetSymbolAddress((void**)&bP0,  g_bP0);
    cudaGetSymbolAddress((void**)&bP1,  g_bP1);

    cudaFuncSetAttribute(mma_gemm, cudaFuncAttributeMaxDynamicSharedMemorySize, GEMM_SMEM);
    cudaFuncSetAttribute(mma_lstm, cudaFuncAttributeMaxDynamicSharedMemorySize, GEMM_SMEM);

    const size_t hElems = (size_t)kM * kH;
    cudaMemsetAsync(c0, 0, hElems * 4);
    cudaMemsetAsync(c1, 0, hElems * 4);
    cudaMemsetAsync(h0h, 0, hElems * 2);   // buffer 0 only
    cudaMemsetAsync(h1h, 0, hElems * 2);

    prep_weights_kernel<<<552, 256>>>(Wi0, Wh0, Wi1, Wh1, Wk, b0, b1,
                                      Wi0T, Wh0T, Wi1T, Wh1T, WkT, bP0, bP1);
    convert_embed_kernel<<<(kV * kH / 4 + 255) / 256, 256>>>(
        (const float4*)embed, (__half2*)embh, kV * kH / 4);

    // G0 = embed @ Wi0 (gate-permuted)  [32000, 1024]
    mma_gemm<<<dim3(k4H / 128, kV / 128), 256, GEMM_SMEM>>>(
        kV, k4H, embh, Wi0T, nullptr, G0, nullptr, 0, nullptr);

    // LSTM: 8 timesteps, 2 layers; h buffers ping-pong (rb -> wb)
    for (int t = 0; t < kL; t++) {
        size_t rb = (size_t)(t & 1) * hElems, wb = (size_t)((t & 1) ^ 1) * hElems;
        mma_lstm<<<dim3(k4H / 128, kM / 128), 256, GEMM_SMEM>>>(
            1, h0h + rb, Wh0T, nullptr, nullptr,
            bP0, G0, data + t, kL,
            c0, h0h + wb, nullptr);
        mma_lstm<<<dim3(k4H / 128, kM / 128), 256, GEMM_SMEM>>>(
            2, h0h + wb, Wi1T, h1h + rb, Wh1T,
            bP1, nullptr, nullptr, 0,
            c1, h1h + wb, (t == kL - 1) ? se : nullptr);
    }
    // final h1 fp16 is in buffer 0 (t=7 writes wb=0); se fp32 also written

    compute_ae_kernel<<<1, 256>>>(edge_table, Wa);

    for (int step = 0; step < kMaxSteps; step++) {
        init_seg_kernel<<<kM / 256, 256>>>();          // zeroes mx/ss/ak/aq
        cudaMemsetAsync(nw, 0, hElems * 4);
        // keys = se @ Wk + bk, with fused partial ak/aq dots
        mma_gemm<<<dim3(kH / 128, kM / 128), 256, GEMM_SMEM>>>(
            kM, kH, h1h, WkT, bk, keys, steps, step, Wa);
        edge_pass1<<<kB * kE / 256, 256>>>(src, dst, et, steps, ba, step);
        edge_pass2<<<kB * kE / 256, 256>>>(dst, steps, step);
        edge_pass3<<<kB * kE * 32 / 256, 256>>>(src, dst, et, steps, edge_table, step);
        masked_copy_kernel<<<kM * kH / 4 / 256, 256>>>(
            steps, step, (const float4*)nw, (float4*)se, (__half2*)h1h);
    }

    final_kernel<<<kB, 256>>>(se, exit_index, Wo, bo, out);
}